// round 12
// baseline (speedup 1.0000x reference)
#include <cuda_runtime.h>
#include <cuda_bf16.h>
#include <cstdint>
#include <math.h>

// Problem constants
#define BB 8
#define SS 512
#define HH 768
#define NHH 12
#define DHH 64
#define LL 12
#define VV 21128
#define FFF 3072
#define PLEN 128
#define NTOK (BB*SS)
#define NVALID_PER_B (SS-PLEN)
#define NVALID (BB*NVALID_PER_B)
#define QKVW (3*HH)            // 2304

// ---------------- scratch (device globals; no allocations allowed) ----------
__device__ float g_h[NTOK*HH];                       // fp32 residual stream
__device__ __nv_bfloat16 g_hhi[NTOK*HH];
__device__ __nv_bfloat16 g_hlo[NTOK*HH];
__device__ __nv_bfloat16 g_qkvh[(size_t)NTOK*QKVW];
__device__ __nv_bfloat16 g_qkvl[(size_t)NTOK*QKVW];
__device__ __nv_bfloat16 g_ctxh[NTOK*HH];
__device__ __nv_bfloat16 g_ctxl[NTOK*HH];
__device__ float g_tmp[NTOK*HH];
__device__ __nv_bfloat16 g_ffnh[(size_t)NTOK*FFF];
__device__ __nv_bfloat16 g_ffnl[(size_t)NTOK*FFF];
__device__ float g_scores[(size_t)BB*NHH*SS*SS];
__device__ __nv_bfloat16 g_schi[(size_t)BB*NHH*SS*SS];
__device__ __nv_bfloat16 g_sclo[(size_t)BB*NHH*SS*SS];
__device__ float g_logits[(size_t)NVALID*VV];
// split weights
__device__ __nv_bfloat16 g_wqkvh[(size_t)LL*HH*QKVW];
__device__ __nv_bfloat16 g_wqkvl[(size_t)LL*HH*QKVW];
__device__ float g_bqkv[(size_t)LL*QKVW];
__device__ __nv_bfloat16 g_woh[(size_t)LL*HH*HH];
__device__ __nv_bfloat16 g_wol[(size_t)LL*HH*HH];
__device__ __nv_bfloat16 g_w1h[(size_t)LL*HH*FFF];
__device__ __nv_bfloat16 g_w1l[(size_t)LL*HH*FFF];
__device__ __nv_bfloat16 g_w2h[(size_t)LL*FFF*HH];
__device__ __nv_bfloat16 g_w2l[(size_t)LL*FFF*HH];
__device__ __nv_bfloat16 g_wch[(size_t)HH*VV];
__device__ __nv_bfloat16 g_wcl[(size_t)HH*VV];
__device__ float g_loss_sum;

// ---------------- helpers ----------------------------------------------------
__device__ __forceinline__ float warpSum(float v){
  #pragma unroll
  for (int o=16;o;o>>=1) v += __shfl_xor_sync(0xffffffffu, v, o);
  return v;
}
__device__ __forceinline__ float warpMax(float v){
  #pragma unroll
  for (int o=16;o;o>>=1) v = fmaxf(v, __shfl_xor_sync(0xffffffffu, v, o));
  return v;
}
template<int NW>
__device__ __forceinline__ float blockSum(float v){
  __shared__ float sh[NW];
  __syncthreads();
  v = warpSum(v);
  if ((threadIdx.x & 31)==0) sh[threadIdx.x>>5] = v;
  __syncthreads();
  float r = 0.f;
  #pragma unroll
  for (int i=0;i<NW;i++) r += sh[i];
  return r;
}
template<int NW>
__device__ __forceinline__ float blockMax(float v){
  __shared__ float sh[NW];
  __syncthreads();
  v = warpMax(v);
  if ((threadIdx.x & 31)==0) sh[threadIdx.x>>5] = v;
  __syncthreads();
  float r = -3.4e38f;
  #pragma unroll
  for (int i=0;i<NW;i++) r = fmaxf(r, sh[i]);
  return r;
}
__device__ __forceinline__ float gelu_exact(float x){
  return 0.5f * x * (1.0f + erff(x * 0.70710678118654752f));
}
__device__ __forceinline__ uint32_t smem_u32(const void* p){
  uint32_t a;
  asm("{ .reg .u64 t; cvta.to.shared.u64 t, %1; cvt.u32.u64 %0, t; }" : "=r"(a) : "l"(p));
  return a;
}
__device__ __forceinline__ void cp16(uint32_t dst, const void* src){
  asm volatile("cp.async.ca.shared.global [%0], [%1], 16;" :: "r"(dst), "l"(src));
}
__device__ __forceinline__ void cp16p(uint32_t dst, const void* src, bool valid){
  int sz = valid ? 16 : 0;
  asm volatile("cp.async.ca.shared.global [%0], [%1], 16, %2;"
               :: "r"(dst), "l"(src), "r"(sz));
}
__device__ __forceinline__ void cp_commit(){
  asm volatile("cp.async.commit_group;" ::: "memory");
}
template<int N>
__device__ __forceinline__ void cp_wait(){
  asm volatile("cp.async.wait_group %0;" :: "n"(N) : "memory");
}

// split a pair of fp32 into packed bf16 hi and lo (x0 -> low half)
__device__ __forceinline__ void split_bf16_pair(float x0, float x1,
                                                uint32_t& hi, uint32_t& lo){
  uint32_t h;
  asm("cvt.rn.bf16x2.f32 %0, %1, %2;" : "=r"(h) : "f"(x1), "f"(x0));
  float h0 = __uint_as_float(h << 16);
  float h1 = __uint_as_float(h & 0xffff0000u);
  float l0 = x0 - h0;
  float l1 = x1 - h1;
  asm("cvt.rn.bf16x2.f32 %0, %1, %2;" : "=r"(lo) : "f"(l1), "f"(l0));
  hi = h;
}
__device__ __forceinline__ void split_bf16_scalar(float x, __nv_bfloat16& h, __nv_bfloat16& l){
  h = __float2bfloat16(x);
  l = __float2bfloat16(x - __bfloat162float(h));
}

__device__ __forceinline__ void mma_bf16(float* d, const uint32_t* a, const uint32_t* b){
  asm volatile(
    "mma.sync.aligned.m16n8k16.row.col.f32.bf16.bf16.f32 "
    "{%0,%1,%2,%3}, {%4,%5,%6,%7}, {%8,%9}, {%0,%1,%2,%3};\n"
    : "+f"(d[0]), "+f"(d[1]), "+f"(d[2]), "+f"(d[3])
    : "r"(a[0]), "r"(a[1]), "r"(a[2]), "r"(a[3]), "r"(b[0]), "r"(b[1]));
}
__device__ __forceinline__ void ldsm_x4(uint32_t* r, uint32_t addr){
  asm volatile("ldmatrix.sync.aligned.m8n8.x4.shared.b16 {%0,%1,%2,%3}, [%4];"
    : "=r"(r[0]), "=r"(r[1]), "=r"(r[2]), "=r"(r[3]) : "r"(addr));
}
__device__ __forceinline__ void ldsm_x4_t(uint32_t* r, uint32_t addr){
  asm volatile("ldmatrix.sync.aligned.m8n8.x4.trans.shared.b16 {%0,%1,%2,%3}, [%4];"
    : "=r"(r[0]), "=r"(r[1]), "=r"(r[2]), "=r"(r[3]) : "r"(addr));
}

// ---------------- 3xBF16 GEMM, pre-split bf16, cp.async 3-stage, BK=32 -------
// C = A @ op(B) (+bias)(+GELU). A,B given as bf16 hi/lo pairs in gmem.
// TRANSB: B is [N,K] (NT). OUT: 0 -> fp32 C; 1 -> bf16 hi/lo C.
// MASK: 0 none; 1 scores (skip CTA if n0>=m0+128); 2 AV (truncate K at m0+128).
// BN=64: warp tile 32x32 (NF=4). BN=128: warp tile 32x64 (NF=8), B fragments
// loaded per 16-col pair and consumed immediately to bound register pressure.
// ONE __syncthreads per 32-K chunk.
template<int BN, bool TRANSB, int ACT, int OUT, int MASK>
__global__ __launch_bounds__(256,2) void gemm_mma(
    const __nv_bfloat16* __restrict__ Agh, const __nv_bfloat16* __restrict__ Agl,
    const __nv_bfloat16* __restrict__ Bgh, const __nv_bfloat16* __restrict__ Bgl,
    const float* __restrict__ bias,
    float* __restrict__ Cf, __nv_bfloat16* __restrict__ Ch, __nv_bfloat16* __restrict__ Cl,
    int M, int N, int K, int lda, int ldb, int ldc,
    int batchInner,
    long long sA1, long long sA2, long long sB1, long long sB2,
    long long sC1, long long sC2)
{
  constexpr int BM = 128;
  constexpr int BK = 32;
  constexpr int STAGES = 3;
  constexpr int WN = BN/2;               // 2 warps across N
  constexpr int MF = 2;                  // WM=32
  constexpr int NF = WN/8;               // 4 or 8

  constexpr int AP = 40;                            // 80B rows: aligned + conflict-free
  constexpr int BROWS = TRANSB ? BN : BK;
  constexpr int BP = TRANSB ? 40 : (BN + 8);        // conflict-free strides
  constexpr int A_EL = BM*AP;
  constexpr int B_EL = BROWS*BP;
  constexpr int STAGE_EL = 2*A_EL + 2*B_EL;

  const int m0 = blockIdx.y * BM;
  const int n0 = blockIdx.x * BN;
  if (MASK == 1 && n0 >= m0 + BM) return;

  extern __shared__ __nv_bfloat16 sm[];

  const int tid  = threadIdx.x;
  const int wid  = tid >> 5;
  const int lane = tid & 31;
  const int grp  = lane >> 2;
  const int tig  = lane & 3;

  const int z  = blockIdx.z;
  const int zo = z / batchInner;
  const int zi = z - zo * batchInner;
  const __nv_bfloat16* Ah_g = Agh + zo*sA1 + zi*sA2;
  const __nv_bfloat16* Al_g = Agl + zo*sA1 + zi*sA2;
  const __nv_bfloat16* Bh_g = Bgh + zo*sB1 + zi*sB2;
  const __nv_bfloat16* Bl_g = Bgl + zo*sB1 + zi*sB2;

  const int wm = (wid >> 1) * 32;
  const int wn = (wid & 1) * WN;

  float acc[MF][NF][4];
  #pragma unroll
  for (int i=0;i<MF;i++)
    #pragma unroll
    for (int j=0;j<NF;j++)
      #pragma unroll
      for (int r=0;r<4;r++) acc[i][j][r] = 0.f;

  int Keff = K;
  if (MASK == 2) Keff = (m0 + BM < K) ? (m0 + BM) : K;
  const int nch = Keff / BK;

  // loader index precompute (BK=32)
  const int aRow = tid >> 2;             // 0..63 (i=0), +64 (i=1)
  const int aQ   = tid & 3;              // 16B quarter within 64B row
  const int bnRow = tid >> 2;            // NT: 0..63 (i loop for BN=128)
  const int bnQ   = tid & 3;
  const int bkK  = tid >> 3;             // NN: 0..31
  const int bkNg = tid & 7;              // NN: n group of 8 (i loop for BN=128)

  auto loadStage = [&](int c, int s){
    const int k0 = c * BK;
    __nv_bfloat16* Ahs = sm + s*STAGE_EL;
    __nv_bfloat16* Als = Ahs + A_EL;
    __nv_bfloat16* Bhs = Als + A_EL;
    __nv_bfloat16* Bls = Bhs + B_EL;
    #pragma unroll
    for (int i=0;i<2;i++){
      int row = aRow + i*64;
      size_t off = (size_t)(m0+row)*lda + k0 + aQ*8;
      cp16(smem_u32(Ahs + row*AP + aQ*8), Ah_g + off);
      cp16(smem_u32(Als + row*AP + aQ*8), Al_g + off);
    }
    if (TRANSB){
      #pragma unroll
      for (int i=0;i<BN/64;i++){
        int row = bnRow + i*64;
        size_t off = (size_t)(n0+row)*ldb + k0 + bnQ*8;
        cp16(smem_u32(Bhs + row*BP + bnQ*8), Bh_g + off);
        cp16(smem_u32(Bls + row*BP + bnQ*8), Bl_g + off);
      }
    } else {
      #pragma unroll
      for (int i=0;i<BN/64;i++){
        int ng = bkNg + i*8;
        int gn = n0 + ng*8;
        bool valid = gn < N;
        size_t off = (size_t)(k0+bkK)*ldb + gn;
        cp16p(smem_u32(Bhs + bkK*BP + ng*8), Bh_g + off, valid);
        cp16p(smem_u32(Bls + bkK*BP + ng*8), Bl_g + off, valid);
      }
    }
  };

  // ldmatrix lane decodes
  const int lrow = lane & 7;
  const int lsel = (lane >> 3) & 1;
  const int lhi  = lane >> 4;

  // ---- prologue: stages 0,1 ----
  loadStage(0, 0); cp_commit();
  loadStage(1, 1); cp_commit();

  for (int c = 0; c < nch; c++){
    const int s = c % STAGES;
    cp_wait<1>();
    __syncthreads();               // the ONLY barrier per chunk

    // prefetch stage c+2 (writes stage (c-1)%3 — safe after the barrier)
    if (c+2 < nch) loadStage(c+2, (c+2) % STAGES);
    cp_commit();

    __nv_bfloat16* Ahs = sm + s*STAGE_EL;
    __nv_bfloat16* Als = Ahs + A_EL;
    __nv_bfloat16* Bhs = Als + A_EL;
    __nv_bfloat16* Bls = Bhs + B_EL;

    #pragma unroll
    for (int ks=0; ks<2; ks++){
      uint32_t ah[MF][4], al[MF][4];
      #pragma unroll
      for (int mf=0; mf<MF; mf++){
        int r = wm + mf*16 + lsel*8 + lrow;
        ldsm_x4(ah[mf], smem_u32(Ahs + r*AP + ks*16 + lhi*8));
        ldsm_x4(al[mf], smem_u32(Als + r*AP + ks*16 + lhi*8));
      }
      #pragma unroll
      for (int nfp=0; nfp<NF/2; nfp++){
        int nb = wn + nfp*16;
        uint32_t rh[4], rl[4];
        if (TRANSB){
          int r = nb + lhi*8 + lrow;
          ldsm_x4(rh, smem_u32(Bhs + r*BP + ks*16 + lsel*8));
          ldsm_x4(rl, smem_u32(Bls + r*BP + ks*16 + lsel*8));
        } else {
          int r = ks*16 + lsel*8 + lrow;
          ldsm_x4_t(rh, smem_u32(Bhs + r*BP + nb + lhi*8));
          ldsm_x4_t(rl, smem_u32(Bls + r*BP + nb + lhi*8));
        }
        #pragma unroll
        for (int mf=0; mf<MF; mf++){
          mma_bf16(acc[mf][2*nfp  ], ah[mf], rh);
          mma_bf16(acc[mf][2*nfp  ], al[mf], rh);
          mma_bf16(acc[mf][2*nfp  ], ah[mf], rl);
          mma_bf16(acc[mf][2*nfp+1], ah[mf], rh+2);
          mma_bf16(acc[mf][2*nfp+1], al[mf], rh+2);
          mma_bf16(acc[mf][2*nfp+1], ah[mf], rl+2);
        }
      }
    }
  }

  float* Cfp = Cf + zo*sC1 + zi*sC2;
  __nv_bfloat16* Chp = Ch + zo*sC1 + zi*sC2;
  __nv_bfloat16* Clp = Cl + zo*sC1 + zi*sC2;

  // ---- epilogue ----
  #pragma unroll
  for (int mf=0; mf<MF; mf++){
    #pragma unroll
    for (int nf=0; nf<NF; nf++){
      int row = m0 + wm + mf*16 + grp;
      int col = n0 + wn + nf*8 + tig*2;
      if (col < N){
        float2 v0 = make_float2(acc[mf][nf][0], acc[mf][nf][1]);
        float2 v1 = make_float2(acc[mf][nf][2], acc[mf][nf][3]);
        if (bias){
          float2 bv = *reinterpret_cast<const float2*>(bias + col);
          v0.x += bv.x; v0.y += bv.y;
          v1.x += bv.x; v1.y += bv.y;
        }
        if (ACT == 1){
          v0.x = gelu_exact(v0.x); v0.y = gelu_exact(v0.y);
          v1.x = gelu_exact(v1.x); v1.y = gelu_exact(v1.y);
        }
        if (OUT == 0){
          *reinterpret_cast<float2*>(Cfp + (size_t)row*ldc + col)     = v0;
          *reinterpret_cast<float2*>(Cfp + (size_t)(row+8)*ldc + col) = v1;
        } else {
          uint32_t h0,l0,h1,l1;
          split_bf16_pair(v0.x, v0.y, h0, l0);
          split_bf16_pair(v1.x, v1.y, h1, l1);
          *reinterpret_cast<uint32_t*>(Chp + (size_t)row*ldc + col)     = h0;
          *reinterpret_cast<uint32_t*>(Clp + (size_t)row*ldc + col)     = l0;
          *reinterpret_cast<uint32_t*>(Chp + (size_t)(row+8)*ldc + col) = h1;
          *reinterpret_cast<uint32_t*>(Clp + (size_t)(row+8)*ldc + col) = l1;
        }
      }
    }
  }
}

// ---------------- weight split kernels ----------------------------------------
__global__ void split2_kernel(const float* __restrict__ src,
                              __nv_bfloat16* __restrict__ hi,
                              __nv_bfloat16* __restrict__ lo, size_t n2)
{
  for (size_t i = (size_t)blockIdx.x*blockDim.x + threadIdx.x;
       i < n2; i += (size_t)gridDim.x*blockDim.x){
    float2 v = reinterpret_cast<const float2*>(src)[i];
    uint32_t h,l; split_bf16_pair(v.x, v.y, h, l);
    reinterpret_cast<uint32_t*>(hi)[i] = h;
    reinterpret_cast<uint32_t*>(lo)[i] = l;
  }
}

__global__ void pack_qkv_split_kernel(const float* __restrict__ Wq,
                                      const float* __restrict__ Wk,
                                      const float* __restrict__ Wv,
                                      const float* __restrict__ bq,
                                      const float* __restrict__ bk,
                                      const float* __restrict__ bv)
{
  const size_t total = (size_t)LL*HH*QKVW;
  for (size_t idx = (size_t)blockIdx.x*blockDim.x + threadIdx.x;
       idx < total; idx += (size_t)gridDim.x*blockDim.x){
    int col = (int)(idx % QKVW);
    size_t rl = idx / QKVW;
    float v;
    if (col < HH)        v = Wq[rl*HH + col];
    else if (col < 2*HH) v = Wk[rl*HH + col - HH];
    else                 v = Wv[rl*HH + col - 2*HH];
    __nv_bfloat16 h,l; split_bf16_scalar(v, h, l);
    g_wqkvh[idx] = h; g_wqkvl[idx] = l;
  }
  for (size_t idx = (size_t)blockIdx.x*blockDim.x + threadIdx.x;
       idx < (size_t)LL*QKVW; idx += (size_t)gridDim.x*blockDim.x){
    int col = (int)(idx % QKVW);
    int l   = (int)(idx / QKVW);
    float v;
    if (col < HH)        v = bq[l*HH + col];
    else if (col < 2*HH) v = bk[l*HH + col - HH];
    else                 v = bv[l*HH + col - 2*HH];
    g_bqkv[idx] = v;
  }
}

// ---------------- embeddings + LN (writes fp32 + bf16 hi/lo) -----------------
__global__ void embed_ln_kernel(const int* __restrict__ ids,
                                const float* __restrict__ we,
                                const float* __restrict__ pe,
                                const float* __restrict__ te,
                                const float* __restrict__ g,
                                const float* __restrict__ b)
{
  int t = blockIdx.x;
  int s = t & (SS-1);
  int id = ids[t];
  const float* wrow = we + (size_t)id*HH;
  const float* prow = pe + (size_t)s*HH;
  float x[3];
  float lsum = 0.f;
  #pragma unroll
  for (int i=0;i<3;i++){
    int c = threadIdx.x + i*256;
    x[i] = wrow[c] + prow[c] + te[c];
    lsum += x[i];
  }
  float mean = blockSum<8>(lsum) * (1.0f/HH);
  float ls2 = 0.f;
  #pragma unroll
  for (int i=0;i<3;i++){ x[i] -= mean; ls2 += x[i]*x[i]; }
  float var = blockSum<8>(ls2) * (1.0f/HH);
  float inv = rsqrtf(var + 1e-12f);
  #pragma unroll
  for (int i=0;i<3;i++){
    int c = threadIdx.x + i*256;
    float v = x[i]*inv*g[c] + b[c];
    g_h[(size_t)t*HH + c] = v;
    __nv_bfloat16 h,l; split_bf16_scalar(v, h, l);
    g_hhi[(size_t)t*HH + c] = h;
    g_hlo[(size_t)t*HH + c] = l;
  }
}

// ---------------- residual + LN (in place on g_h; emits hi/lo too) -----------
__global__ void resln_kernel(const float* __restrict__ r,
                             const float* __restrict__ g,
                             const float* __restrict__ b)
{
  int t = blockIdx.x;
  float x[3];
  float lsum = 0.f;
  #pragma unroll
  for (int i=0;i<3;i++){
    int c = threadIdx.x + i*256;
    x[i] = g_h[(size_t)t*HH + c] + r[(size_t)t*HH + c];
    lsum += x[i];
  }
  float mean = blockSum<8>(lsum) * (1.0f/HH);
  float ls2 = 0.f;
  #pragma unroll
  for (int i=0;i<3;i++){ x[i] -= mean; ls2 += x[i]*x[i]; }
  float var = blockSum<8>(ls2) * (1.0f/HH);
  float inv = rsqrtf(var + 1e-12f);
  #pragma unroll
  for (int i=0;i<3;i++){
    int c = threadIdx.x + i*256;
    float v = x[i]*inv*g[c] + b[c];
    g_h[(size_t)t*HH + c] = v;
    __nv_bfloat16 h,l; split_bf16_scalar(v, h, l);
    g_hhi[(size_t)t*HH + c] = h;
    g_hlo[(size_t)t*HH + c] = l;
  }
}

// ---------------- masked softmax (fp32 in -> bf16 hi/lo out, truncated) ------
__global__ void softmax_kernel()
{
  int z = blockIdx.y;
  int s = blockIdx.x;
  const size_t base = ((size_t)z*SS + s)*SS;
  const float* row = g_scores + base;
  const int L = (s < PLEN) ? PLEN : (s + 1);
  const int E = (s/128 + 1) * 128;
  float x[4];
  float mx = -3.4e38f;
  #pragma unroll
  for (int i=0;i<4;i++){
    int j = threadIdx.x + i*128;
    x[i] = (j < L) ? row[j] * 0.125f : -3.4e38f;
    mx = fmaxf(mx, x[i]);
  }
  mx = blockMax<4>(mx);
  float ls = 0.f;
  #pragma unroll
  for (int i=0;i<4;i++){
    int j = threadIdx.x + i*128;
    x[i] = (j < L) ? __expf(x[i] - mx) : 0.f;
    ls += x[i];
  }
  float sum = blockSum<4>(ls);
  float inv = 1.0f / sum;
  #pragma unroll
  for (int i=0;i<4;i++){
    int j = threadIdx.x + i*128;
    if (j < L){
      float v = x[i] * inv;
      __nv_bfloat16 h,l; split_bf16_scalar(v, h, l);
      g_schi[base + j] = h;
      g_sclo[base + j] = l;
    } else if (j < E){
      g_schi[base + j] = __float2bfloat16(0.f);
      g_sclo[base + j] = __float2bfloat16(0.f);
    }
  }
}

// ---------------- cross entropy over valid rows ------------------------------
__global__ void zero_loss_kernel(){ g_loss_sum = 0.f; }

__global__ void ce_kernel(const int* __restrict__ labels)
{
  int r = blockIdx.x;
  int bb = r / NVALID_PER_B;
  int s  = PLEN + (r - bb*NVALID_PER_B);
  const float* row = g_logits + (size_t)r*VV;
  int lab = labels[bb*SS + s];

  float mx = -3.4e38f;
  for (int j = threadIdx.x; j < VV; j += 256) mx = fmaxf(mx, row[j]);
  mx = blockMax<8>(mx);
  float ls = 0.f;
  for (int j = threadIdx.x; j < VV; j += 256) ls += __expf(row[j] - mx);
  float sum = blockSum<8>(ls);
  if (threadIdx.x == 0){
    float nll = (logf(sum) + mx) - row[lab];
    atomicAdd(&g_loss_sum, nll);
  }
}

__global__ void finalize_kernel(float* out){
  out[0] = g_loss_sum * (1.0f/(float)NVALID);
}

// ---------------- host orchestration -----------------------------------------
template<int BN, bool TRANSB, int ACT, int OUT, int MASK>
static void launch_mm(const __nv_bfloat16* Ah, const __nv_bfloat16* Al,
                      const __nv_bfloat16* Bh, const __nv_bfloat16* Bl,
                      const float* bias,
                      float* Cf, __nv_bfloat16* Ch, __nv_bfloat16* Cl,
                      int M, int N, int K, int lda, int ldb, int ldc,
                      int batchInner,
                      long long sA1, long long sA2, long long sB1, long long sB2,
                      long long sC1, long long sC2, int gz)
{
  constexpr int AP = 40;
  constexpr int BROWS = TRANSB ? BN : 32;
  constexpr int BP = TRANSB ? 40 : (BN + 8);
  constexpr int STAGE_EL = 2*128*AP + 2*BROWS*BP;
  int smemsz = 3 * STAGE_EL * (int)sizeof(__nv_bfloat16);
  cudaFuncSetAttribute(gemm_mma<BN,TRANSB,ACT,OUT,MASK>,
                       cudaFuncAttributeMaxDynamicSharedMemorySize, smemsz);
  dim3 grid((N + BN - 1)/BN, M/128, gz);
  gemm_mma<BN,TRANSB,ACT,OUT,MASK><<<grid, 256, smemsz>>>(
      Ah, Al, Bh, Bl, bias, Cf, Ch, Cl, M, N, K, lda, ldb, ldc,
      batchInner, sA1, sA2, sB1, sB2, sC1, sC2);
}

extern "C" void kernel_launch(void* const* d_in, const int* in_sizes, int n_in,
                              void* d_out, int out_size)
{
  const int*   input_ids = (const int*)  d_in[0];
  const int*   labels    = (const int*)  d_in[1];
  const float* word_emb  = (const float*)d_in[2];
  const float* pos_emb   = (const float*)d_in[3];
  const float* type_emb  = (const float*)d_in[4];
  const float* eg        = (const float*)d_in[5];
  const float* eb        = (const float*)d_in[6];
  const float* Wq = (const float*)d_in[7];  const float* bq = (const float*)d_in[8];
  const float* Wk = (const float*)d_in[9];  const float* bk = (const float*)d_in[10];
  const float* Wv = (const float*)d_in[11]; const float* bv = (const float*)d_in[12];
  const float* Wo = (const float*)d_in[13]; const float* bo = (const float*)d_in[14];
  const float* ln1g = (const float*)d_in[15]; const float* ln1b = (const float*)d_in[16];
  const float* W1 = (const float*)d_in[17]; const float* bf1 = (const float*)d_in[18];
  const float* W2 = (const float*)d_in[19]; const float* bf2 = (const float*)d_in[20];
  const float* ln2g = (const float*)d_in[21]; const float* ln2b = (const float*)d_in[22];
  const float* Wc = (const float*)d_in[23]; const float* bc = (const float*)d_in[24];
  float* out = (float*)d_out;

  float *p_tmp, *p_sc, *p_lg, *p_bqkv;
  __nv_bfloat16 *p_hhi, *p_hlo, *p_qkvh, *p_qkvl, *p_ctxh, *p_ctxl;
  __nv_bfloat16 *p_ffnh, *p_ffnl, *p_schi, *p_sclo;
  __nv_bfloat16 *p_wqkvh, *p_wqkvl, *p_woh, *p_wol, *p_w1h, *p_w1l, *p_w2h, *p_w2l, *p_wch, *p_wcl;
  cudaGetSymbolAddress((void**)&p_tmp,  g_tmp);
  cudaGetSymbolAddress((void**)&p_sc,   g_scores);
  cudaGetSymbolAddress((void**)&p_lg,   g_logits);
  cudaGetSymbolAddress((void**)&p_bqkv, g_bqkv);
  cudaGetSymbolAddress((void**)&p_hhi,  g_hhi);
  cudaGetSymbolAddress((void**)&p_hlo,  g_hlo);
  cudaGetSymbolAddress((void**)&p_qkvh, g_qkvh);
  cudaGetSymbolAddress((void**)&p_qkvl, g_qkvl);
  cudaGetSymbolAddress((void**)&p_ctxh, g_ctxh);
  cudaGetSymbolAddress((void**)&p_ctxl, g_ctxl);
  cudaGetSymbolAddress((void**)&p_ffnh, g_ffnh);
  cudaGetSymbolAddress((void**)&p_ffnl, g_ffnl);
  cudaGetSymbolAddress((void**)&p_schi, g_schi);
  cudaGetSymbolAddress((void**)&p_sclo, g_sclo);
  cudaGetSymbolAddress((void**)&p_wqkvh, g_wqkvh);
  cudaGetSymbolAddress((void**)&p_wqkvl, g_wqkvl);
  cudaGetSymbolAddress((void**)&p_woh, g_woh);
  cudaGetSymbolAddress((void**)&p_wol, g_wol);
  cudaGetSymbolAddress((void**)&p_w1h, g_w1h);
  cudaGetSymbolAddress((void**)&p_w1l, g_w1l);
  cudaGetSymbolAddress((void**)&p_w2h, g_w2h);
  cudaGetSymbolAddress((void**)&p_w2l, g_w2l);
  cudaGetSymbolAddress((void**)&p_wch, g_wch);
  cudaGetSymbolAddress((void**)&p_wcl, g_wcl);

  zero_loss_kernel<<<1,1>>>();
  pack_qkv_split_kernel<<<1024,256>>>(Wq, Wk, Wv, bq, bk, bv);
  split2_kernel<<<1024,256>>>(Wo, p_woh, p_wol, (size_t)LL*HH*HH/2);
  split2_kernel<<<1024,256>>>(W1, p_w1h, p_w1l, (size_t)LL*HH*FFF/2);
  split2_kernel<<<1024,256>>>(W2, p_w2h, p_w2l, (size_t)LL*FFF*HH/2);
  split2_kernel<<<1024,256>>>(Wc, p_wch, p_wcl, (size_t)HH*VV/2);
  embed_ln_kernel<<<NTOK,256>>>(input_ids, word_emb, pos_emb, type_emb, eg, eb);

  const long long headStride = (long long)SS*HH;
  const long long qkvBatch   = (long long)SS*QKVW;
  const long long scStrideH  = (long long)SS*SS;
  const long long scStrideB  = (long long)NHH*SS*SS;

  for (int l = 0; l < LL; l++) {
    // fused QKV projection: [4096,768] @ [768,2304] + b -> bf16 hi/lo  (BN=128)
    launch_mm<128,false,0,1,0>(p_hhi, p_hlo,
                               p_wqkvh + (size_t)l*HH*QKVW, p_wqkvl + (size_t)l*HH*QKVW,
                               p_bqkv + (size_t)l*QKVW,
                               nullptr, p_qkvh, p_qkvl,
                               NTOK, QKVW, HH, HH, QKVW, QKVW,
                               1, 0,0, 0,0, 0,0, 1);

    // scores = q @ k^T (NT), dead tiles skipped -> fp32  (BN=64)
    launch_mm<64,true,0,0,1>(p_qkvh, p_qkvl, p_qkvh + HH, p_qkvl + HH,
                             nullptr, p_sc, nullptr, nullptr,
                             SS, SS, DHH, QKVW, QKVW, SS,
                             NHH,
                             qkvBatch, (long long)DHH,
                             qkvBatch, (long long)DHH,
                             scStrideB, scStrideH, BB*NHH);

    softmax_kernel<<<dim3(SS, BB*NHH), 128>>>();

    // ctx = attn @ v (NN), K truncated -> bf16 hi/lo  (BN=64, N=64)
    launch_mm<64,false,0,1,2>(p_schi, p_sclo, p_qkvh + 2*HH, p_qkvl + 2*HH,
                              nullptr, nullptr, p_ctxh, p_ctxl,
                              SS, DHH, SS, SS, QKVW, HH,
                              NHH,
                              scStrideB, scStrideH,
                              qkvBatch, (long long)DHH,
                              headStride, (long long)DHH, BB*NHH);

    // output proj -> fp32 g_tmp, then residual LN  (BN=128)
    launch_mm<128,false,0,0,0>(p_ctxh, p_ctxl,
                               p_woh + (size_t)l*HH*HH, p_wol + (size_t)l*HH*HH,
                               bo + (size_t)l*HH,
                               p_tmp, nullptr, nullptr,
                               NTOK, HH, HH, HH, HH, HH,
                               1, 0,0, 0,0, 0,0, 1);
    resln_kernel<<<NTOK,256>>>(p_tmp, ln1g + (size_t)l*HH, ln1b + (size_t)l*HH);

    // FFN1 (+GELU) -> bf16 hi/lo  (BN=128)
    launch_mm<128,false,1,1,0>(p_hhi, p_hlo,
                               p_w1h + (size_t)l*HH*FFF, p_w1l + (size_t)l*HH*FFF,
                               bf1 + (size_t)l*FFF,
                               nullptr, p_ffnh, p_ffnl,
                               NTOK, FFF, HH, HH, FFF, FFF,
                               1, 0,0, 0,0, 0,0, 1);
    // FFN2 -> fp32 g_tmp, then residual LN  (BN=128)
    launch_mm<128,false,0,0,0>(p_ffnh, p_ffnl,
                               p_w2h + (size_t)l*FFF*HH, p_w2l + (size_t)l*FFF*HH,
                               bf2 + (size_t)l*HH,
                               p_tmp, nullptr, nullptr,
                               NTOK, HH, FFF, FFF, HH, HH,
                               1, 0,0, 0,0, 0,0, 1);
    resln_kernel<<<NTOK,256>>>(p_tmp, ln2g + (size_t)l*HH, ln2b + (size_t)l*HH);
  }

  // logits for valid tokens only (rows s in [128,512) per batch)  (BN=128)
  launch_mm<128,false,0,0,0>(p_hhi + (size_t)PLEN*HH, p_hlo + (size_t)PLEN*HH,
                             p_wch, p_wcl, bc,
                             p_lg, nullptr, nullptr,
                             NVALID_PER_B, VV, HH, HH, VV, VV,
                             1,
                             (long long)SS*HH, 0,
                             0, 0,
                             (long long)NVALID_PER_B*VV, 0, BB);

  ce_kernel<<<NVALID,256>>>(labels);
  finalize_kernel<<<1,1>>>(out);
}

// round 13
// speedup vs baseline: 1.0576x; 1.0576x over previous
#include <cuda_runtime.h>
#include <cuda_bf16.h>
#include <cstdint>
#include <math.h>

// Problem constants
#define BB 8
#define SS 512
#define HH 768
#define NHH 12
#define DHH 64
#define LL 12
#define VV 21128
#define FFF 3072
#define PLEN 128
#define NTOK (BB*SS)
#define NVALID_PER_B (SS-PLEN)
#define NVALID (BB*NVALID_PER_B)
#define QKVW (3*HH)            // 2304

// ---------------- scratch (device globals; no allocations allowed) ----------
__device__ float g_h[NTOK*HH];                       // fp32 residual stream
__device__ __nv_bfloat16 g_hhi[NTOK*HH];
__device__ __nv_bfloat16 g_hlo[NTOK*HH];
__device__ __nv_bfloat16 g_qkvh[(size_t)NTOK*QKVW];
__device__ __nv_bfloat16 g_qkvl[(size_t)NTOK*QKVW];
__device__ __nv_bfloat16 g_ctxh[NTOK*HH];
__device__ __nv_bfloat16 g_ctxl[NTOK*HH];
__device__ float g_tmp[NTOK*HH];
__device__ __nv_bfloat16 g_ffnh[(size_t)NTOK*FFF];
__device__ __nv_bfloat16 g_ffnl[(size_t)NTOK*FFF];
__device__ float g_scores[(size_t)BB*NHH*SS*SS];
__device__ __nv_bfloat16 g_schi[(size_t)BB*NHH*SS*SS];
__device__ __nv_bfloat16 g_sclo[(size_t)BB*NHH*SS*SS];
__device__ float g_logits[(size_t)NVALID*VV];
// split weights
__device__ __nv_bfloat16 g_wqkvh[(size_t)LL*HH*QKVW];
__device__ __nv_bfloat16 g_wqkvl[(size_t)LL*HH*QKVW];
__device__ float g_bqkv[(size_t)LL*QKVW];
__device__ __nv_bfloat16 g_woh[(size_t)LL*HH*HH];
__device__ __nv_bfloat16 g_wol[(size_t)LL*HH*HH];
__device__ __nv_bfloat16 g_w1h[(size_t)LL*HH*FFF];
__device__ __nv_bfloat16 g_w1l[(size_t)LL*HH*FFF];
__device__ __nv_bfloat16 g_w2h[(size_t)LL*FFF*HH];
__device__ __nv_bfloat16 g_w2l[(size_t)LL*FFF*HH];
__device__ __nv_bfloat16 g_wch[(size_t)HH*VV];
__device__ __nv_bfloat16 g_wcl[(size_t)HH*VV];
__device__ float g_loss_sum;

// ---------------- helpers ----------------------------------------------------
__device__ __forceinline__ float warpSum(float v){
  #pragma unroll
  for (int o=16;o;o>>=1) v += __shfl_xor_sync(0xffffffffu, v, o);
  return v;
}
__device__ __forceinline__ float warpMax(float v){
  #pragma unroll
  for (int o=16;o;o>>=1) v = fmaxf(v, __shfl_xor_sync(0xffffffffu, v, o));
  return v;
}
template<int NW>
__device__ __forceinline__ float blockSum(float v){
  __shared__ float sh[NW];
  __syncthreads();
  v = warpSum(v);
  if ((threadIdx.x & 31)==0) sh[threadIdx.x>>5] = v;
  __syncthreads();
  float r = 0.f;
  #pragma unroll
  for (int i=0;i<NW;i++) r += sh[i];
  return r;
}
template<int NW>
__device__ __forceinline__ float blockMax(float v){
  __shared__ float sh[NW];
  __syncthreads();
  v = warpMax(v);
  if ((threadIdx.x & 31)==0) sh[threadIdx.x>>5] = v;
  __syncthreads();
  float r = -3.4e38f;
  #pragma unroll
  for (int i=0;i<NW;i++) r = fmaxf(r, sh[i]);
  return r;
}
__device__ __forceinline__ float gelu_exact(float x){
  return 0.5f * x * (1.0f + erff(x * 0.70710678118654752f));
}
__device__ __forceinline__ uint32_t smem_u32(const void* p){
  uint32_t a;
  asm("{ .reg .u64 t; cvta.to.shared.u64 t, %1; cvt.u32.u64 %0, t; }" : "=r"(a) : "l"(p));
  return a;
}
__device__ __forceinline__ void cp16(uint32_t dst, const void* src){
  asm volatile("cp.async.ca.shared.global [%0], [%1], 16;" :: "r"(dst), "l"(src));
}
__device__ __forceinline__ void cp16p(uint32_t dst, const void* src, bool valid){
  int sz = valid ? 16 : 0;
  asm volatile("cp.async.ca.shared.global [%0], [%1], 16, %2;"
               :: "r"(dst), "l"(src), "r"(sz));
}
__device__ __forceinline__ void cp_commit(){
  asm volatile("cp.async.commit_group;" ::: "memory");
}
template<int N>
__device__ __forceinline__ void cp_wait(){
  asm volatile("cp.async.wait_group %0;" :: "n"(N) : "memory");
}

// split a pair of fp32 into packed bf16 hi and lo (x0 -> low half)
__device__ __forceinline__ void split_bf16_pair(float x0, float x1,
                                                uint32_t& hi, uint32_t& lo){
  uint32_t h;
  asm("cvt.rn.bf16x2.f32 %0, %1, %2;" : "=r"(h) : "f"(x1), "f"(x0));
  float h0 = __uint_as_float(h << 16);
  float h1 = __uint_as_float(h & 0xffff0000u);
  float l0 = x0 - h0;
  float l1 = x1 - h1;
  asm("cvt.rn.bf16x2.f32 %0, %1, %2;" : "=r"(lo) : "f"(l1), "f"(l0));
  hi = h;
}
__device__ __forceinline__ void split_bf16_scalar(float x, __nv_bfloat16& h, __nv_bfloat16& l){
  h = __float2bfloat16(x);
  l = __float2bfloat16(x - __bfloat162float(h));
}

__device__ __forceinline__ void mma_bf16(float* d, const uint32_t* a, const uint32_t* b){
  asm volatile(
    "mma.sync.aligned.m16n8k16.row.col.f32.bf16.bf16.f32 "
    "{%0,%1,%2,%3}, {%4,%5,%6,%7}, {%8,%9}, {%0,%1,%2,%3};\n"
    : "+f"(d[0]), "+f"(d[1]), "+f"(d[2]), "+f"(d[3])
    : "r"(a[0]), "r"(a[1]), "r"(a[2]), "r"(a[3]), "r"(b[0]), "r"(b[1]));
}
__device__ __forceinline__ void ldsm_x4(uint32_t* r, uint32_t addr){
  asm volatile("ldmatrix.sync.aligned.m8n8.x4.shared.b16 {%0,%1,%2,%3}, [%4];"
    : "=r"(r[0]), "=r"(r[1]), "=r"(r[2]), "=r"(r[3]) : "r"(addr));
}
__device__ __forceinline__ void ldsm_x4_t(uint32_t* r, uint32_t addr){
  asm volatile("ldmatrix.sync.aligned.m8n8.x4.trans.shared.b16 {%0,%1,%2,%3}, [%4];"
    : "=r"(r[0]), "=r"(r[1]), "=r"(r[2]), "=r"(r[3]) : "r"(addr));
}

// ---------------- 3xBF16 GEMM, pre-split bf16, cp.async 3-stage, BK=32 -------
// C = A @ op(B) (+bias)(+GELU). A,B given as bf16 hi/lo pairs in gmem.
// TRANSB: B is [N,K] (NT). OUT: 0 -> fp32 C; 1 -> bf16 hi/lo C.
// MASK: 0 none; 1 scores (skip CTA if n0>=m0+128); 2 AV (truncate K at m0+128).
// BN=64, warp tile 32x32, ONE __syncthreads per 32-K chunk.
// MMA issued in 3 independent passes (hh, lh, hl) to break accumulator RAW chains.
template<int BN, bool TRANSB, int ACT, int OUT, int MASK>
__global__ __launch_bounds__(256,2) void gemm_mma(
    const __nv_bfloat16* __restrict__ Agh, const __nv_bfloat16* __restrict__ Agl,
    const __nv_bfloat16* __restrict__ Bgh, const __nv_bfloat16* __restrict__ Bgl,
    const float* __restrict__ bias,
    float* __restrict__ Cf, __nv_bfloat16* __restrict__ Ch, __nv_bfloat16* __restrict__ Cl,
    int M, int N, int K, int lda, int ldb, int ldc,
    int batchInner,
    long long sA1, long long sA2, long long sB1, long long sB2,
    long long sC1, long long sC2)
{
  constexpr int BM = 128;
  constexpr int BK = 32;
  constexpr int STAGES = 3;
  constexpr int WM = 32, WN = 32;
  constexpr int MF = 2, NF = 4;
  constexpr int WARPS_N = BN/32;         // 2

  constexpr int AP = 40;                            // 80B rows: aligned + conflict-free
  constexpr int BROWS = TRANSB ? BN : BK;
  constexpr int BP = TRANSB ? 40 : (BN + 8);        // 80B / 144B rows
  constexpr int A_EL = BM*AP;
  constexpr int B_EL = BROWS*BP;
  constexpr int STAGE_EL = 2*A_EL + 2*B_EL;

  const int m0 = blockIdx.y * BM;
  const int n0 = blockIdx.x * BN;
  if (MASK == 1 && n0 >= m0 + BM) return;

  extern __shared__ __nv_bfloat16 sm[];

  const int tid  = threadIdx.x;
  const int wid  = tid >> 5;
  const int lane = tid & 31;
  const int grp  = lane >> 2;
  const int tig  = lane & 3;

  const int z  = blockIdx.z;
  const int zo = z / batchInner;
  const int zi = z - zo * batchInner;
  const __nv_bfloat16* Ah_g = Agh + zo*sA1 + zi*sA2;
  const __nv_bfloat16* Al_g = Agl + zo*sA1 + zi*sA2;
  const __nv_bfloat16* Bh_g = Bgh + zo*sB1 + zi*sB2;
  const __nv_bfloat16* Bl_g = Bgl + zo*sB1 + zi*sB2;

  const int wm = (wid / WARPS_N) * WM;
  const int wn = (wid % WARPS_N) * WN;

  float acc[MF][NF][4];
  #pragma unroll
  for (int i=0;i<MF;i++)
    #pragma unroll
    for (int j=0;j<NF;j++)
      #pragma unroll
      for (int r=0;r<4;r++) acc[i][j][r] = 0.f;

  int Keff = K;
  if (MASK == 2) Keff = (m0 + BM < K) ? (m0 + BM) : K;
  const int nch = Keff / BK;

  // loader index precompute (BK=32)
  const int aRow = tid >> 2;             // 0..63 (i=0), +64 (i=1)
  const int aQ   = tid & 3;              // 16B quarter within 64B row
  const int bnRow = tid >> 2;            // NT: 0..63
  const int bnQ   = tid & 3;
  const int bkK  = tid >> 3;             // NN: 0..31
  const int bkNg = tid & 7;              // NN: n group (8 bf16)

  auto loadStage = [&](int c, int s){
    const int k0 = c * BK;
    __nv_bfloat16* Ahs = sm + s*STAGE_EL;
    __nv_bfloat16* Als = Ahs + A_EL;
    __nv_bfloat16* Bhs = Als + A_EL;
    __nv_bfloat16* Bls = Bhs + B_EL;
    #pragma unroll
    for (int i=0;i<2;i++){
      int row = aRow + i*64;
      size_t off = (size_t)(m0+row)*lda + k0 + aQ*8;
      cp16(smem_u32(Ahs + row*AP + aQ*8), Ah_g + off);
      cp16(smem_u32(Als + row*AP + aQ*8), Al_g + off);
    }
    if (TRANSB){
      size_t off = (size_t)(n0+bnRow)*ldb + k0 + bnQ*8;
      cp16(smem_u32(Bhs + bnRow*BP + bnQ*8), Bh_g + off);
      cp16(smem_u32(Bls + bnRow*BP + bnQ*8), Bl_g + off);
    } else {
      int gn = n0 + bkNg*8;
      bool valid = gn < N;
      size_t off = (size_t)(k0+bkK)*ldb + gn;
      cp16p(smem_u32(Bhs + bkK*BP + bkNg*8), Bh_g + off, valid);
      cp16p(smem_u32(Bls + bkK*BP + bkNg*8), Bl_g + off, valid);
    }
  };

  // ldmatrix lane decodes
  const int lrow = lane & 7;
  const int lsel = (lane >> 3) & 1;
  const int lhi  = lane >> 4;

  // ---- prologue: stages 0,1 ----
  loadStage(0, 0); cp_commit();
  loadStage(1, 1); cp_commit();

  for (int c = 0; c < nch; c++){
    const int s = c % STAGES;
    cp_wait<1>();
    __syncthreads();               // the ONLY barrier per chunk

    // prefetch stage c+2 (writes stage (c-1)%3 — safe after the barrier)
    if (c+2 < nch) loadStage(c+2, (c+2) % STAGES);
    cp_commit();

    __nv_bfloat16* Ahs = sm + s*STAGE_EL;
    __nv_bfloat16* Als = Ahs + A_EL;
    __nv_bfloat16* Bhs = Als + A_EL;
    __nv_bfloat16* Bls = Bhs + B_EL;

    #pragma unroll
    for (int ks=0; ks<2; ks++){
      uint32_t ah[MF][4], al[MF][4];
      #pragma unroll
      for (int mf=0; mf<MF; mf++){
        int r = wm + mf*16 + lsel*8 + lrow;
        ldsm_x4(ah[mf], smem_u32(Ahs + r*AP + ks*16 + lhi*8));
        ldsm_x4(al[mf], smem_u32(Als + r*AP + ks*16 + lhi*8));
      }
      uint32_t bh[NF][2], bl[NF][2];
      #pragma unroll
      for (int nfp=0; nfp<NF/2; nfp++){
        int nb = wn + nfp*16;
        uint32_t rh[4], rl[4];
        if (TRANSB){
          int r = nb + lhi*8 + lrow;
          ldsm_x4(rh, smem_u32(Bhs + r*BP + ks*16 + lsel*8));
          ldsm_x4(rl, smem_u32(Bls + r*BP + ks*16 + lsel*8));
        } else {
          int r = ks*16 + lsel*8 + lrow;
          ldsm_x4_t(rh, smem_u32(Bhs + r*BP + nb + lhi*8));
          ldsm_x4_t(rl, smem_u32(Bls + r*BP + nb + lhi*8));
        }
        bh[2*nfp][0]=rh[0]; bh[2*nfp][1]=rh[1]; bh[2*nfp+1][0]=rh[2]; bh[2*nfp+1][1]=rh[3];
        bl[2*nfp][0]=rl[0]; bl[2*nfp][1]=rl[1]; bl[2*nfp+1][0]=rl[2]; bl[2*nfp+1][1]=rl[3];
      }
      // three independent passes: 8 independent MMAs between acc reuses
      #pragma unroll
      for (int mf=0; mf<MF; mf++)
        #pragma unroll
        for (int nf=0; nf<NF; nf++)
          mma_bf16(acc[mf][nf], ah[mf], bh[nf]);
      #pragma unroll
      for (int mf=0; mf<MF; mf++)
        #pragma unroll
        for (int nf=0; nf<NF; nf++)
          mma_bf16(acc[mf][nf], al[mf], bh[nf]);
      #pragma unroll
      for (int mf=0; mf<MF; mf++)
        #pragma unroll
        for (int nf=0; nf<NF; nf++)
          mma_bf16(acc[mf][nf], ah[mf], bl[nf]);
    }
  }

  float* Cfp = Cf + zo*sC1 + zi*sC2;
  __nv_bfloat16* Chp = Ch + zo*sC1 + zi*sC2;
  __nv_bfloat16* Clp = Cl + zo*sC1 + zi*sC2;

  // ---- epilogue ----
  #pragma unroll
  for (int mf=0; mf<MF; mf++){
    #pragma unroll
    for (int nf=0; nf<NF; nf++){
      int row = m0 + wm + mf*16 + grp;
      int col = n0 + wn + nf*8 + tig*2;
      if (col < N){
        float2 v0 = make_float2(acc[mf][nf][0], acc[mf][nf][1]);
        float2 v1 = make_float2(acc[mf][nf][2], acc[mf][nf][3]);
        if (bias){
          float2 bv = *reinterpret_cast<const float2*>(bias + col);
          v0.x += bv.x; v0.y += bv.y;
          v1.x += bv.x; v1.y += bv.y;
        }
        if (ACT == 1){
          v0.x = gelu_exact(v0.x); v0.y = gelu_exact(v0.y);
          v1.x = gelu_exact(v1.x); v1.y = gelu_exact(v1.y);
        }
        if (OUT == 0){
          *reinterpret_cast<float2*>(Cfp + (size_t)row*ldc + col)     = v0;
          *reinterpret_cast<float2*>(Cfp + (size_t)(row+8)*ldc + col) = v1;
        } else {
          uint32_t h0,l0,h1,l1;
          split_bf16_pair(v0.x, v0.y, h0, l0);
          split_bf16_pair(v1.x, v1.y, h1, l1);
          *reinterpret_cast<uint32_t*>(Chp + (size_t)row*ldc + col)     = h0;
          *reinterpret_cast<uint32_t*>(Clp + (size_t)row*ldc + col)     = l0;
          *reinterpret_cast<uint32_t*>(Chp + (size_t)(row+8)*ldc + col) = h1;
          *reinterpret_cast<uint32_t*>(Clp + (size_t)(row+8)*ldc + col) = l1;
        }
      }
    }
  }
}

// ---------------- weight split kernels ----------------------------------------
__global__ void split2_kernel(const float* __restrict__ src,
                              __nv_bfloat16* __restrict__ hi,
                              __nv_bfloat16* __restrict__ lo, size_t n2)
{
  for (size_t i = (size_t)blockIdx.x*blockDim.x + threadIdx.x;
       i < n2; i += (size_t)gridDim.x*blockDim.x){
    float2 v = reinterpret_cast<const float2*>(src)[i];
    uint32_t h,l; split_bf16_pair(v.x, v.y, h, l);
    reinterpret_cast<uint32_t*>(hi)[i] = h;
    reinterpret_cast<uint32_t*>(lo)[i] = l;
  }
}

__global__ void pack_qkv_split_kernel(const float* __restrict__ Wq,
                                      const float* __restrict__ Wk,
                                      const float* __restrict__ Wv,
                                      const float* __restrict__ bq,
                                      const float* __restrict__ bk,
                                      const float* __restrict__ bv)
{
  const size_t total = (size_t)LL*HH*QKVW;
  for (size_t idx = (size_t)blockIdx.x*blockDim.x + threadIdx.x;
       idx < total; idx += (size_t)gridDim.x*blockDim.x){
    int col = (int)(idx % QKVW);
    size_t rl = idx / QKVW;
    float v;
    if (col < HH)        v = Wq[rl*HH + col];
    else if (col < 2*HH) v = Wk[rl*HH + col - HH];
    else                 v = Wv[rl*HH + col - 2*HH];
    __nv_bfloat16 h,l; split_bf16_scalar(v, h, l);
    g_wqkvh[idx] = h; g_wqkvl[idx] = l;
  }
  for (size_t idx = (size_t)blockIdx.x*blockDim.x + threadIdx.x;
       idx < (size_t)LL*QKVW; idx += (size_t)gridDim.x*blockDim.x){
    int col = (int)(idx % QKVW);
    int l   = (int)(idx / QKVW);
    float v;
    if (col < HH)        v = bq[l*HH + col];
    else if (col < 2*HH) v = bk[l*HH + col - HH];
    else                 v = bv[l*HH + col - 2*HH];
    g_bqkv[idx] = v;
  }
}

// ---------------- embeddings + LN (writes fp32 + bf16 hi/lo) -----------------
__global__ void embed_ln_kernel(const int* __restrict__ ids,
                                const float* __restrict__ we,
                                const float* __restrict__ pe,
                                const float* __restrict__ te,
                                const float* __restrict__ g,
                                const float* __restrict__ b)
{
  int t = blockIdx.x;
  int s = t & (SS-1);
  int id = ids[t];
  const float* wrow = we + (size_t)id*HH;
  const float* prow = pe + (size_t)s*HH;
  float x[3];
  float lsum = 0.f;
  #pragma unroll
  for (int i=0;i<3;i++){
    int c = threadIdx.x + i*256;
    x[i] = wrow[c] + prow[c] + te[c];
    lsum += x[i];
  }
  float mean = blockSum<8>(lsum) * (1.0f/HH);
  float ls2 = 0.f;
  #pragma unroll
  for (int i=0;i<3;i++){ x[i] -= mean; ls2 += x[i]*x[i]; }
  float var = blockSum<8>(ls2) * (1.0f/HH);
  float inv = rsqrtf(var + 1e-12f);
  #pragma unroll
  for (int i=0;i<3;i++){
    int c = threadIdx.x + i*256;
    float v = x[i]*inv*g[c] + b[c];
    g_h[(size_t)t*HH + c] = v;
    __nv_bfloat16 h,l; split_bf16_scalar(v, h, l);
    g_hhi[(size_t)t*HH + c] = h;
    g_hlo[(size_t)t*HH + c] = l;
  }
}

// ---------------- residual + LN (in place on g_h; emits hi/lo too) -----------
__global__ void resln_kernel(const float* __restrict__ r,
                             const float* __restrict__ g,
                             const float* __restrict__ b)
{
  int t = blockIdx.x;
  float x[3];
  float lsum = 0.f;
  #pragma unroll
  for (int i=0;i<3;i++){
    int c = threadIdx.x + i*256;
    x[i] = g_h[(size_t)t*HH + c] + r[(size_t)t*HH + c];
    lsum += x[i];
  }
  float mean = blockSum<8>(lsum) * (1.0f/HH);
  float ls2 = 0.f;
  #pragma unroll
  for (int i=0;i<3;i++){ x[i] -= mean; ls2 += x[i]*x[i]; }
  float var = blockSum<8>(ls2) * (1.0f/HH);
  float inv = rsqrtf(var + 1e-12f);
  #pragma unroll
  for (int i=0;i<3;i++){
    int c = threadIdx.x + i*256;
    float v = x[i]*inv*g[c] + b[c];
    g_h[(size_t)t*HH + c] = v;
    __nv_bfloat16 h,l; split_bf16_scalar(v, h, l);
    g_hhi[(size_t)t*HH + c] = h;
    g_hlo[(size_t)t*HH + c] = l;
  }
}

// ---------------- masked softmax (fp32 in -> bf16 hi/lo out, truncated) ------
__global__ void softmax_kernel()
{
  int z = blockIdx.y;
  int s = blockIdx.x;
  const size_t base = ((size_t)z*SS + s)*SS;
  const float* row = g_scores + base;
  const int L = (s < PLEN) ? PLEN : (s + 1);
  const int E = (s/128 + 1) * 128;
  float x[4];
  float mx = -3.4e38f;
  #pragma unroll
  for (int i=0;i<4;i++){
    int j = threadIdx.x + i*128;
    x[i] = (j < L) ? row[j] * 0.125f : -3.4e38f;
    mx = fmaxf(mx, x[i]);
  }
  mx = blockMax<4>(mx);
  float ls = 0.f;
  #pragma unroll
  for (int i=0;i<4;i++){
    int j = threadIdx.x + i*128;
    x[i] = (j < L) ? __expf(x[i] - mx) : 0.f;
    ls += x[i];
  }
  float sum = blockSum<4>(ls);
  float inv = 1.0f / sum;
  #pragma unroll
  for (int i=0;i<4;i++){
    int j = threadIdx.x + i*128;
    if (j < L){
      float v = x[i] * inv;
      __nv_bfloat16 h,l; split_bf16_scalar(v, h, l);
      g_schi[base + j] = h;
      g_sclo[base + j] = l;
    } else if (j < E){
      g_schi[base + j] = __float2bfloat16(0.f);
      g_sclo[base + j] = __float2bfloat16(0.f);
    }
  }
}

// ---------------- cross entropy (single pass, online logsumexp) --------------
__global__ void zero_loss_kernel(){ g_loss_sum = 0.f; }

__global__ void ce_kernel(const int* __restrict__ labels)
{
  int r = blockIdx.x;
  int bb = r / NVALID_PER_B;
  int s  = PLEN + (r - bb*NVALID_PER_B);
  const float* row = g_logits + (size_t)r*VV;
  int lab = labels[bb*SS + s];

  // per-thread online (max, sum) in one pass
  float mx = -3.4e38f;
  float sm = 0.f;
  for (int j = threadIdx.x; j < VV; j += 256){
    float v = row[j];
    if (v > mx){
      sm = sm * __expf(mx - v) + 1.0f;
      mx = v;
    } else {
      sm += __expf(v - mx);
    }
  }
  float bM = blockMax<8>(mx);
  float contrib = (sm > 0.f) ? sm * __expf(mx - bM) : 0.f;
  float total = blockSum<8>(contrib);
  if (threadIdx.x == 0){
    float nll = (logf(total) + bM) - row[lab];
    atomicAdd(&g_loss_sum, nll);
  }
}

__global__ void finalize_kernel(float* out){
  out[0] = g_loss_sum * (1.0f/(float)NVALID);
}

// ---------------- host orchestration -----------------------------------------
template<int BN, bool TRANSB, int ACT, int OUT, int MASK>
static void launch_mm(const __nv_bfloat16* Ah, const __nv_bfloat16* Al,
                      const __nv_bfloat16* Bh, const __nv_bfloat16* Bl,
                      const float* bias,
                      float* Cf, __nv_bfloat16* Ch, __nv_bfloat16* Cl,
                      int M, int N, int K, int lda, int ldb, int ldc,
                      int batchInner,
                      long long sA1, long long sA2, long long sB1, long long sB2,
                      long long sC1, long long sC2, int gz)
{
  constexpr int AP = 40;
  constexpr int BROWS = TRANSB ? BN : 32;
  constexpr int BP = TRANSB ? 40 : (BN + 8);
  constexpr int STAGE_EL = 2*128*AP + 2*BROWS*BP;
  int smemsz = 3 * STAGE_EL * (int)sizeof(__nv_bfloat16);
  cudaFuncSetAttribute(gemm_mma<BN,TRANSB,ACT,OUT,MASK>,
                       cudaFuncAttributeMaxDynamicSharedMemorySize, smemsz);
  dim3 grid((N + BN - 1)/BN, M/128, gz);
  gemm_mma<BN,TRANSB,ACT,OUT,MASK><<<grid, 256, smemsz>>>(
      Ah, Al, Bh, Bl, bias, Cf, Ch, Cl, M, N, K, lda, ldb, ldc,
      batchInner, sA1, sA2, sB1, sB2, sC1, sC2);
}

extern "C" void kernel_launch(void* const* d_in, const int* in_sizes, int n_in,
                              void* d_out, int out_size)
{
  const int*   input_ids = (const int*)  d_in[0];
  const int*   labels    = (const int*)  d_in[1];
  const float* word_emb  = (const float*)d_in[2];
  const float* pos_emb   = (const float*)d_in[3];
  const float* type_emb  = (const float*)d_in[4];
  const float* eg        = (const float*)d_in[5];
  const float* eb        = (const float*)d_in[6];
  const float* Wq = (const float*)d_in[7];  const float* bq = (const float*)d_in[8];
  const float* Wk = (const float*)d_in[9];  const float* bk = (const float*)d_in[10];
  const float* Wv = (const float*)d_in[11]; const float* bv = (const float*)d_in[12];
  const float* Wo = (const float*)d_in[13]; const float* bo = (const float*)d_in[14];
  const float* ln1g = (const float*)d_in[15]; const float* ln1b = (const float*)d_in[16];
  const float* W1 = (const float*)d_in[17]; const float* bf1 = (const float*)d_in[18];
  const float* W2 = (const float*)d_in[19]; const float* bf2 = (const float*)d_in[20];
  const float* ln2g = (const float*)d_in[21]; const float* ln2b = (const float*)d_in[22];
  const float* Wc = (const float*)d_in[23]; const float* bc = (const float*)d_in[24];
  float* out = (float*)d_out;

  float *p_tmp, *p_sc, *p_lg, *p_bqkv;
  __nv_bfloat16 *p_hhi, *p_hlo, *p_qkvh, *p_qkvl, *p_ctxh, *p_ctxl;
  __nv_bfloat16 *p_ffnh, *p_ffnl, *p_schi, *p_sclo;
  __nv_bfloat16 *p_wqkvh, *p_wqkvl, *p_woh, *p_wol, *p_w1h, *p_w1l, *p_w2h, *p_w2l, *p_wch, *p_wcl;
  cudaGetSymbolAddress((void**)&p_tmp,  g_tmp);
  cudaGetSymbolAddress((void**)&p_sc,   g_scores);
  cudaGetSymbolAddress((void**)&p_lg,   g_logits);
  cudaGetSymbolAddress((void**)&p_bqkv, g_bqkv);
  cudaGetSymbolAddress((void**)&p_hhi,  g_hhi);
  cudaGetSymbolAddress((void**)&p_hlo,  g_hlo);
  cudaGetSymbolAddress((void**)&p_qkvh, g_qkvh);
  cudaGetSymbolAddress((void**)&p_qkvl, g_qkvl);
  cudaGetSymbolAddress((void**)&p_ctxh, g_ctxh);
  cudaGetSymbolAddress((void**)&p_ctxl, g_ctxl);
  cudaGetSymbolAddress((void**)&p_ffnh, g_ffnh);
  cudaGetSymbolAddress((void**)&p_ffnl, g_ffnl);
  cudaGetSymbolAddress((void**)&p_schi, g_schi);
  cudaGetSymbolAddress((void**)&p_sclo, g_sclo);
  cudaGetSymbolAddress((void**)&p_wqkvh, g_wqkvh);
  cudaGetSymbolAddress((void**)&p_wqkvl, g_wqkvl);
  cudaGetSymbolAddress((void**)&p_woh, g_woh);
  cudaGetSymbolAddress((void**)&p_wol, g_wol);
  cudaGetSymbolAddress((void**)&p_w1h, g_w1h);
  cudaGetSymbolAddress((void**)&p_w1l, g_w1l);
  cudaGetSymbolAddress((void**)&p_w2h, g_w2h);
  cudaGetSymbolAddress((void**)&p_w2l, g_w2l);
  cudaGetSymbolAddress((void**)&p_wch, g_wch);
  cudaGetSymbolAddress((void**)&p_wcl, g_wcl);

  zero_loss_kernel<<<1,1>>>();
  pack_qkv_split_kernel<<<1024,256>>>(Wq, Wk, Wv, bq, bk, bv);
  split2_kernel<<<1024,256>>>(Wo, p_woh, p_wol, (size_t)LL*HH*HH/2);
  split2_kernel<<<1024,256>>>(W1, p_w1h, p_w1l, (size_t)LL*HH*FFF/2);
  split2_kernel<<<1024,256>>>(W2, p_w2h, p_w2l, (size_t)LL*FFF*HH/2);
  split2_kernel<<<1024,256>>>(Wc, p_wch, p_wcl, (size_t)HH*VV/2);
  embed_ln_kernel<<<NTOK,256>>>(input_ids, word_emb, pos_emb, type_emb, eg, eb);

  const long long headStride = (long long)SS*HH;
  const long long qkvBatch   = (long long)SS*QKVW;
  const long long scStrideH  = (long long)SS*SS;
  const long long scStrideB  = (long long)NHH*SS*SS;

  for (int l = 0; l < LL; l++) {
    // fused QKV projection: [4096,768] @ [768,2304] + b -> bf16 hi/lo
    launch_mm<64,false,0,1,0>(p_hhi, p_hlo,
                              p_wqkvh + (size_t)l*HH*QKVW, p_wqkvl + (size_t)l*HH*QKVW,
                              p_bqkv + (size_t)l*QKVW,
                              nullptr, p_qkvh, p_qkvl,
                              NTOK, QKVW, HH, HH, QKVW, QKVW,
                              1, 0,0, 0,0, 0,0, 1);

    // scores = q @ k^T (NT), dead tiles skipped -> fp32
    launch_mm<64,true,0,0,1>(p_qkvh, p_qkvl, p_qkvh + HH, p_qkvl + HH,
                             nullptr, p_sc, nullptr, nullptr,
                             SS, SS, DHH, QKVW, QKVW, SS,
                             NHH,
                             qkvBatch, (long long)DHH,
                             qkvBatch, (long long)DHH,
                             scStrideB, scStrideH, BB*NHH);

    softmax_kernel<<<dim3(SS, BB*NHH), 128>>>();

    // ctx = attn @ v (NN), K truncated -> bf16 hi/lo
    launch_mm<64,false,0,1,2>(p_schi, p_sclo, p_qkvh + 2*HH, p_qkvl + 2*HH,
                              nullptr, nullptr, p_ctxh, p_ctxl,
                              SS, DHH, SS, SS, QKVW, HH,
                              NHH,
                              scStrideB, scStrideH,
                              qkvBatch, (long long)DHH,
                              headStride, (long long)DHH, BB*NHH);

    // output proj -> fp32 g_tmp, then residual LN
    launch_mm<64,false,0,0,0>(p_ctxh, p_ctxl,
                              p_woh + (size_t)l*HH*HH, p_wol + (size_t)l*HH*HH,
                              bo + (size_t)l*HH,
                              p_tmp, nullptr, nullptr,
                              NTOK, HH, HH, HH, HH, HH,
                              1, 0,0, 0,0, 0,0, 1);
    resln_kernel<<<NTOK,256>>>(p_tmp, ln1g + (size_t)l*HH, ln1b + (size_t)l*HH);

    // FFN1 (+GELU) -> bf16 hi/lo
    launch_mm<64,false,1,1,0>(p_hhi, p_hlo,
                              p_w1h + (size_t)l*HH*FFF, p_w1l + (size_t)l*HH*FFF,
                              bf1 + (size_t)l*FFF,
                              nullptr, p_ffnh, p_ffnl,
                              NTOK, FFF, HH, HH, FFF, FFF,
                              1, 0,0, 0,0, 0,0, 1);
    // FFN2 -> fp32 g_tmp, then residual LN
    launch_mm<64,false,0,0,0>(p_ffnh, p_ffnl,
                              p_w2h + (size_t)l*FFF*HH, p_w2l + (size_t)l*FFF*HH,
                              bf2 + (size_t)l*HH,
                              p_tmp, nullptr, nullptr,
                              NTOK, HH, FFF, FFF, HH, HH,
                              1, 0,0, 0,0, 0,0, 1);
    resln_kernel<<<NTOK,256>>>(p_tmp, ln2g + (size_t)l*HH, ln2b + (size_t)l*HH);
  }

  // logits for valid tokens only (rows s in [128,512) per batch, contiguous)
  launch_mm<64,false,0,0,0>(p_hhi + (size_t)PLEN*HH, p_hlo + (size_t)PLEN*HH,
                            p_wch, p_wcl, bc,
                            p_lg, nullptr, nullptr,
                            NVALID_PER_B, VV, HH, HH, VV, VV,
                            1,
                            (long long)SS*HH, 0,
                            0, 0,
                            (long long)NVALID_PER_B*VV, 0, BB);

  ce_kernel<<<NVALID,256>>>(labels);
  finalize_kernel<<<1,1>>>(out);
}

// round 14
// speedup vs baseline: 1.0634x; 1.0055x over previous
#include <cuda_runtime.h>
#include <cuda_bf16.h>
#include <cstdint>
#include <math.h>

// Problem constants
#define BB 8
#define SS 512
#define HH 768
#define NHH 12
#define DHH 64
#define LL 12
#define VV 21128
#define FFF 3072
#define PLEN 128
#define NTOK (BB*SS)
#define NVALID_PER_B (SS-PLEN)
#define NVALID (BB*NVALID_PER_B)
#define QKVW (3*HH)            // 2304

// ---------------- scratch (device globals; no allocations allowed) ----------
__device__ float g_h[NTOK*HH];                       // fp32 residual stream
__device__ __nv_bfloat16 g_hhi[NTOK*HH];
__device__ __nv_bfloat16 g_hlo[NTOK*HH];
__device__ __nv_bfloat16 g_qkvh[(size_t)NTOK*QKVW];
__device__ __nv_bfloat16 g_qkvl[(size_t)NTOK*QKVW];
__device__ __nv_bfloat16 g_ctxh[NTOK*HH];
__device__ __nv_bfloat16 g_ctxl[NTOK*HH];
__device__ float g_tmp[NTOK*HH];
__device__ __nv_bfloat16 g_ffnh[(size_t)NTOK*FFF];
__device__ __nv_bfloat16 g_ffnl[(size_t)NTOK*FFF];
__device__ float g_scores[(size_t)BB*NHH*SS*SS];
__device__ __nv_bfloat16 g_schi[(size_t)BB*NHH*SS*SS];
__device__ __nv_bfloat16 g_sclo[(size_t)BB*NHH*SS*SS];
__device__ float g_logits[(size_t)NVALID*VV];
// split weights
__device__ __nv_bfloat16 g_wqkvh[(size_t)LL*HH*QKVW];
__device__ __nv_bfloat16 g_wqkvl[(size_t)LL*HH*QKVW];
__device__ float g_bqkv[(size_t)LL*QKVW];
__device__ __nv_bfloat16 g_woh[(size_t)LL*HH*HH];
__device__ __nv_bfloat16 g_wol[(size_t)LL*HH*HH];
__device__ __nv_bfloat16 g_w1h[(size_t)LL*HH*FFF];
__device__ __nv_bfloat16 g_w1l[(size_t)LL*HH*FFF];
__device__ __nv_bfloat16 g_w2h[(size_t)LL*FFF*HH];
__device__ __nv_bfloat16 g_w2l[(size_t)LL*FFF*HH];
__device__ __nv_bfloat16 g_wch[(size_t)HH*VV];
__device__ __nv_bfloat16 g_wcl[(size_t)HH*VV];
__device__ float g_loss_sum;

// ---------------- helpers ----------------------------------------------------
__device__ __forceinline__ float warpSum(float v){
  #pragma unroll
  for (int o=16;o;o>>=1) v += __shfl_xor_sync(0xffffffffu, v, o);
  return v;
}
__device__ __forceinline__ float warpMax(float v){
  #pragma unroll
  for (int o=16;o;o>>=1) v = fmaxf(v, __shfl_xor_sync(0xffffffffu, v, o));
  return v;
}
template<int NW>
__device__ __forceinline__ float blockSum(float v){
  __shared__ float sh[NW];
  __syncthreads();
  v = warpSum(v);
  if ((threadIdx.x & 31)==0) sh[threadIdx.x>>5] = v;
  __syncthreads();
  float r = 0.f;
  #pragma unroll
  for (int i=0;i<NW;i++) r += sh[i];
  return r;
}
template<int NW>
__device__ __forceinline__ float blockMax(float v){
  __shared__ float sh[NW];
  __syncthreads();
  v = warpMax(v);
  if ((threadIdx.x & 31)==0) sh[threadIdx.x>>5] = v;
  __syncthreads();
  float r = -3.4e38f;
  #pragma unroll
  for (int i=0;i<NW;i++) r = fmaxf(r, sh[i]);
  return r;
}
__device__ __forceinline__ float gelu_exact(float x){
  return 0.5f * x * (1.0f + erff(x * 0.70710678118654752f));
}
__device__ __forceinline__ uint32_t smem_u32(const void* p){
  uint32_t a;
  asm("{ .reg .u64 t; cvta.to.shared.u64 t, %1; cvt.u32.u64 %0, t; }" : "=r"(a) : "l"(p));
  return a;
}
__device__ __forceinline__ void cp16(uint32_t dst, const void* src){
  asm volatile("cp.async.ca.shared.global [%0], [%1], 16;" :: "r"(dst), "l"(src));
}
__device__ __forceinline__ void cp16p(uint32_t dst, const void* src, bool valid){
  int sz = valid ? 16 : 0;
  asm volatile("cp.async.ca.shared.global [%0], [%1], 16, %2;"
               :: "r"(dst), "l"(src), "r"(sz));
}
__device__ __forceinline__ void cp_commit(){
  asm volatile("cp.async.commit_group;" ::: "memory");
}
template<int N>
__device__ __forceinline__ void cp_wait(){
  asm volatile("cp.async.wait_group %0;" :: "n"(N) : "memory");
}

// split a pair of fp32 into packed bf16 hi and lo (x0 -> low half)
__device__ __forceinline__ void split_bf16_pair(float x0, float x1,
                                                uint32_t& hi, uint32_t& lo){
  uint32_t h;
  asm("cvt.rn.bf16x2.f32 %0, %1, %2;" : "=r"(h) : "f"(x1), "f"(x0));
  float h0 = __uint_as_float(h << 16);
  float h1 = __uint_as_float(h & 0xffff0000u);
  float l0 = x0 - h0;
  float l1 = x1 - h1;
  asm("cvt.rn.bf16x2.f32 %0, %1, %2;" : "=r"(lo) : "f"(l1), "f"(l0));
  hi = h;
}
__device__ __forceinline__ void split_bf16_scalar(float x, __nv_bfloat16& h, __nv_bfloat16& l){
  h = __float2bfloat16(x);
  l = __float2bfloat16(x - __bfloat162float(h));
}

__device__ __forceinline__ void mma_bf16(float* d, const uint32_t* a, const uint32_t* b){
  asm volatile(
    "mma.sync.aligned.m16n8k16.row.col.f32.bf16.bf16.f32 "
    "{%0,%1,%2,%3}, {%4,%5,%6,%7}, {%8,%9}, {%0,%1,%2,%3};\n"
    : "+f"(d[0]), "+f"(d[1]), "+f"(d[2]), "+f"(d[3])
    : "r"(a[0]), "r"(a[1]), "r"(a[2]), "r"(a[3]), "r"(b[0]), "r"(b[1]));
}
__device__ __forceinline__ void ldsm_x4(uint32_t* r, uint32_t addr){
  asm volatile("ldmatrix.sync.aligned.m8n8.x4.shared.b16 {%0,%1,%2,%3}, [%4];"
    : "=r"(r[0]), "=r"(r[1]), "=r"(r[2]), "=r"(r[3]) : "r"(addr));
}
__device__ __forceinline__ void ldsm_x4_t(uint32_t* r, uint32_t addr){
  asm volatile("ldmatrix.sync.aligned.m8n8.x4.trans.shared.b16 {%0,%1,%2,%3}, [%4];"
    : "=r"(r[0]), "=r"(r[1]), "=r"(r[2]), "=r"(r[3]) : "r"(addr));
}

// ---------------- 3xBF16 GEMM, pre-split bf16, cp.async 3-stage, BK=32 -------
// C = A @ op(B) (+bias)(+GELU). A,B given as bf16 hi/lo pairs in gmem.
// TRANSB: B is [N,K] (NT). OUT: 0 -> fp32 C; 1 -> bf16 hi/lo C.
// MASK: 0 none; 1 scores (skip CTA if n0>=m0+128); 2 AV (truncate K at m0+128).
// BN=64, warp tile 32x32, ONE __syncthreads per 32-K chunk.
// MMA issued in 3 independent passes (hh, lh, hl) to break accumulator RAW chains.
template<int BN, bool TRANSB, int ACT, int OUT, int MASK>
__global__ __launch_bounds__(256,2) void gemm_mma(
    const __nv_bfloat16* __restrict__ Agh, const __nv_bfloat16* __restrict__ Agl,
    const __nv_bfloat16* __restrict__ Bgh, const __nv_bfloat16* __restrict__ Bgl,
    const float* __restrict__ bias,
    float* __restrict__ Cf, __nv_bfloat16* __restrict__ Ch, __nv_bfloat16* __restrict__ Cl,
    int M, int N, int K, int lda, int ldb, int ldc,
    int batchInner,
    long long sA1, long long sA2, long long sB1, long long sB2,
    long long sC1, long long sC2)
{
  constexpr int BM = 128;
  constexpr int BK = 32;
  constexpr int STAGES = 3;
  constexpr int WM = 32, WN = 32;
  constexpr int MF = 2, NF = 4;
  constexpr int WARPS_N = BN/32;         // 2

  constexpr int AP = 40;                            // 80B rows: aligned + conflict-free
  constexpr int BROWS = TRANSB ? BN : BK;
  constexpr int BP = TRANSB ? 40 : (BN + 8);        // 80B / 144B rows
  constexpr int A_EL = BM*AP;
  constexpr int B_EL = BROWS*BP;
  constexpr int STAGE_EL = 2*A_EL + 2*B_EL;

  const int m0 = blockIdx.y * BM;
  const int n0 = blockIdx.x * BN;
  if (MASK == 1 && n0 >= m0 + BM) return;

  extern __shared__ __nv_bfloat16 sm[];

  const int tid  = threadIdx.x;
  const int wid  = tid >> 5;
  const int lane = tid & 31;
  const int grp  = lane >> 2;
  const int tig  = lane & 3;

  const int z  = blockIdx.z;
  const int zo = z / batchInner;
  const int zi = z - zo * batchInner;
  const __nv_bfloat16* Ah_g = Agh + zo*sA1 + zi*sA2;
  const __nv_bfloat16* Al_g = Agl + zo*sA1 + zi*sA2;
  const __nv_bfloat16* Bh_g = Bgh + zo*sB1 + zi*sB2;
  const __nv_bfloat16* Bl_g = Bgl + zo*sB1 + zi*sB2;

  const int wm = (wid / WARPS_N) * WM;
  const int wn = (wid % WARPS_N) * WN;

  float acc[MF][NF][4];
  #pragma unroll
  for (int i=0;i<MF;i++)
    #pragma unroll
    for (int j=0;j<NF;j++)
      #pragma unroll
      for (int r=0;r<4;r++) acc[i][j][r] = 0.f;

  int Keff = K;
  if (MASK == 2) Keff = (m0 + BM < K) ? (m0 + BM) : K;
  const int nch = Keff / BK;

  // loader index precompute (BK=32)
  const int aRow = tid >> 2;             // 0..63 (i=0), +64 (i=1)
  const int aQ   = tid & 3;              // 16B quarter within 64B row
  const int bnRow = tid >> 2;            // NT: 0..63
  const int bnQ   = tid & 3;
  const int bkK  = tid >> 3;             // NN: 0..31
  const int bkNg = tid & 7;              // NN: n group (8 bf16)

  auto loadStage = [&](int c, int s){
    const int k0 = c * BK;
    __nv_bfloat16* Ahs = sm + s*STAGE_EL;
    __nv_bfloat16* Als = Ahs + A_EL;
    __nv_bfloat16* Bhs = Als + A_EL;
    __nv_bfloat16* Bls = Bhs + B_EL;
    #pragma unroll
    for (int i=0;i<2;i++){
      int row = aRow + i*64;
      size_t off = (size_t)(m0+row)*lda + k0 + aQ*8;
      cp16(smem_u32(Ahs + row*AP + aQ*8), Ah_g + off);
      cp16(smem_u32(Als + row*AP + aQ*8), Al_g + off);
    }
    if (TRANSB){
      size_t off = (size_t)(n0+bnRow)*ldb + k0 + bnQ*8;
      cp16(smem_u32(Bhs + bnRow*BP + bnQ*8), Bh_g + off);
      cp16(smem_u32(Bls + bnRow*BP + bnQ*8), Bl_g + off);
    } else {
      int gn = n0 + bkNg*8;
      bool valid = gn < N;
      size_t off = (size_t)(k0+bkK)*ldb + gn;
      cp16p(smem_u32(Bhs + bkK*BP + bkNg*8), Bh_g + off, valid);
      cp16p(smem_u32(Bls + bkK*BP + bkNg*8), Bl_g + off, valid);
    }
  };

  // ldmatrix lane decodes
  const int lrow = lane & 7;
  const int lsel = (lane >> 3) & 1;
  const int lhi  = lane >> 4;

  // ---- prologue: stages 0,1 ----
  loadStage(0, 0); cp_commit();
  loadStage(1, 1); cp_commit();

  for (int c = 0; c < nch; c++){
    const int s = c % STAGES;
    cp_wait<1>();
    __syncthreads();               // the ONLY barrier per chunk

    // prefetch stage c+2 (writes stage (c-1)%3 — safe after the barrier)
    if (c+2 < nch) loadStage(c+2, (c+2) % STAGES);
    cp_commit();

    __nv_bfloat16* Ahs = sm + s*STAGE_EL;
    __nv_bfloat16* Als = Ahs + A_EL;
    __nv_bfloat16* Bhs = Als + A_EL;
    __nv_bfloat16* Bls = Bhs + B_EL;

    #pragma unroll
    for (int ks=0; ks<2; ks++){
      uint32_t ah[MF][4], al[MF][4];
      #pragma unroll
      for (int mf=0; mf<MF; mf++){
        int r = wm + mf*16 + lsel*8 + lrow;
        ldsm_x4(ah[mf], smem_u32(Ahs + r*AP + ks*16 + lhi*8));
        ldsm_x4(al[mf], smem_u32(Als + r*AP + ks*16 + lhi*8));
      }
      uint32_t bh[NF][2], bl[NF][2];
      #pragma unroll
      for (int nfp=0; nfp<NF/2; nfp++){
        int nb = wn + nfp*16;
        uint32_t rh[4], rl[4];
        if (TRANSB){
          int r = nb + lhi*8 + lrow;
          ldsm_x4(rh, smem_u32(Bhs + r*BP + ks*16 + lsel*8));
          ldsm_x4(rl, smem_u32(Bls + r*BP + ks*16 + lsel*8));
        } else {
          int r = ks*16 + lsel*8 + lrow;
          ldsm_x4_t(rh, smem_u32(Bhs + r*BP + nb + lhi*8));
          ldsm_x4_t(rl, smem_u32(Bls + r*BP + nb + lhi*8));
        }
        bh[2*nfp][0]=rh[0]; bh[2*nfp][1]=rh[1]; bh[2*nfp+1][0]=rh[2]; bh[2*nfp+1][1]=rh[3];
        bl[2*nfp][0]=rl[0]; bl[2*nfp][1]=rl[1]; bl[2*nfp+1][0]=rl[2]; bl[2*nfp+1][1]=rl[3];
      }
      // three independent passes: 8 independent MMAs between acc reuses
      #pragma unroll
      for (int mf=0; mf<MF; mf++)
        #pragma unroll
        for (int nf=0; nf<NF; nf++)
          mma_bf16(acc[mf][nf], ah[mf], bh[nf]);
      #pragma unroll
      for (int mf=0; mf<MF; mf++)
        #pragma unroll
        for (int nf=0; nf<NF; nf++)
          mma_bf16(acc[mf][nf], al[mf], bh[nf]);
      #pragma unroll
      for (int mf=0; mf<MF; mf++)
        #pragma unroll
        for (int nf=0; nf<NF; nf++)
          mma_bf16(acc[mf][nf], ah[mf], bl[nf]);
    }
  }

  float* Cfp = Cf + zo*sC1 + zi*sC2;
  __nv_bfloat16* Chp = Ch + zo*sC1 + zi*sC2;
  __nv_bfloat16* Clp = Cl + zo*sC1 + zi*sC2;

  // ---- epilogue ----
  #pragma unroll
  for (int mf=0; mf<MF; mf++){
    #pragma unroll
    for (int nf=0; nf<NF; nf++){
      int row = m0 + wm + mf*16 + grp;
      int col = n0 + wn + nf*8 + tig*2;
      if (col < N){
        float2 v0 = make_float2(acc[mf][nf][0], acc[mf][nf][1]);
        float2 v1 = make_float2(acc[mf][nf][2], acc[mf][nf][3]);
        if (bias){
          float2 bv = *reinterpret_cast<const float2*>(bias + col);
          v0.x += bv.x; v0.y += bv.y;
          v1.x += bv.x; v1.y += bv.y;
        }
        if (ACT == 1){
          v0.x = gelu_exact(v0.x); v0.y = gelu_exact(v0.y);
          v1.x = gelu_exact(v1.x); v1.y = gelu_exact(v1.y);
        }
        if (OUT == 0){
          *reinterpret_cast<float2*>(Cfp + (size_t)row*ldc + col)     = v0;
          *reinterpret_cast<float2*>(Cfp + (size_t)(row+8)*ldc + col) = v1;
        } else {
          uint32_t h0,l0,h1,l1;
          split_bf16_pair(v0.x, v0.y, h0, l0);
          split_bf16_pair(v1.x, v1.y, h1, l1);
          *reinterpret_cast<uint32_t*>(Chp + (size_t)row*ldc + col)     = h0;
          *reinterpret_cast<uint32_t*>(Clp + (size_t)row*ldc + col)     = l0;
          *reinterpret_cast<uint32_t*>(Chp + (size_t)(row+8)*ldc + col) = h1;
          *reinterpret_cast<uint32_t*>(Clp + (size_t)(row+8)*ldc + col) = l1;
        }
      }
    }
  }
}

// ---------------- weight split kernels ----------------------------------------
__global__ void split2_kernel(const float* __restrict__ src,
                              __nv_bfloat16* __restrict__ hi,
                              __nv_bfloat16* __restrict__ lo, size_t n2)
{
  for (size_t i = (size_t)blockIdx.x*blockDim.x + threadIdx.x;
       i < n2; i += (size_t)gridDim.x*blockDim.x){
    float2 v = reinterpret_cast<const float2*>(src)[i];
    uint32_t h,l; split_bf16_pair(v.x, v.y, h, l);
    reinterpret_cast<uint32_t*>(hi)[i] = h;
    reinterpret_cast<uint32_t*>(lo)[i] = l;
  }
}

__global__ void pack_qkv_split_kernel(const float* __restrict__ Wq,
                                      const float* __restrict__ Wk,
                                      const float* __restrict__ Wv,
                                      const float* __restrict__ bq,
                                      const float* __restrict__ bk,
                                      const float* __restrict__ bv)
{
  const size_t total = (size_t)LL*HH*QKVW;
  for (size_t idx = (size_t)blockIdx.x*blockDim.x + threadIdx.x;
       idx < total; idx += (size_t)gridDim.x*blockDim.x){
    int col = (int)(idx % QKVW);
    size_t rl = idx / QKVW;
    float v;
    if (col < HH)        v = Wq[rl*HH + col];
    else if (col < 2*HH) v = Wk[rl*HH + col - HH];
    else                 v = Wv[rl*HH + col - 2*HH];
    __nv_bfloat16 h,l; split_bf16_scalar(v, h, l);
    g_wqkvh[idx] = h; g_wqkvl[idx] = l;
  }
  for (size_t idx = (size_t)blockIdx.x*blockDim.x + threadIdx.x;
       idx < (size_t)LL*QKVW; idx += (size_t)gridDim.x*blockDim.x){
    int col = (int)(idx % QKVW);
    int l   = (int)(idx / QKVW);
    float v;
    if (col < HH)        v = bq[l*HH + col];
    else if (col < 2*HH) v = bk[l*HH + col - HH];
    else                 v = bv[l*HH + col - 2*HH];
    g_bqkv[idx] = v;
  }
}

// ---------------- embeddings + LN (writes fp32 + bf16 hi/lo) -----------------
__global__ void embed_ln_kernel(const int* __restrict__ ids,
                                const float* __restrict__ we,
                                const float* __restrict__ pe,
                                const float* __restrict__ te,
                                const float* __restrict__ g,
                                const float* __restrict__ b)
{
  int t = blockIdx.x;
  int s = t & (SS-1);
  int id = ids[t];
  const float* wrow = we + (size_t)id*HH;
  const float* prow = pe + (size_t)s*HH;
  float x[3];
  float lsum = 0.f;
  #pragma unroll
  for (int i=0;i<3;i++){
    int c = threadIdx.x + i*256;
    x[i] = wrow[c] + prow[c] + te[c];
    lsum += x[i];
  }
  float mean = blockSum<8>(lsum) * (1.0f/HH);
  float ls2 = 0.f;
  #pragma unroll
  for (int i=0;i<3;i++){ x[i] -= mean; ls2 += x[i]*x[i]; }
  float var = blockSum<8>(ls2) * (1.0f/HH);
  float inv = rsqrtf(var + 1e-12f);
  #pragma unroll
  for (int i=0;i<3;i++){
    int c = threadIdx.x + i*256;
    float v = x[i]*inv*g[c] + b[c];
    g_h[(size_t)t*HH + c] = v;
    __nv_bfloat16 h,l; split_bf16_scalar(v, h, l);
    g_hhi[(size_t)t*HH + c] = h;
    g_hlo[(size_t)t*HH + c] = l;
  }
}

// ---------------- residual + LN (in place on g_h; emits hi/lo too) -----------
__global__ void resln_kernel(const float* __restrict__ r,
                             const float* __restrict__ g,
                             const float* __restrict__ b)
{
  int t = blockIdx.x;
  float x[3];
  float lsum = 0.f;
  #pragma unroll
  for (int i=0;i<3;i++){
    int c = threadIdx.x + i*256;
    x[i] = g_h[(size_t)t*HH + c] + r[(size_t)t*HH + c];
    lsum += x[i];
  }
  float mean = blockSum<8>(lsum) * (1.0f/HH);
  float ls2 = 0.f;
  #pragma unroll
  for (int i=0;i<3;i++){ x[i] -= mean; ls2 += x[i]*x[i]; }
  float var = blockSum<8>(ls2) * (1.0f/HH);
  float inv = rsqrtf(var + 1e-12f);
  #pragma unroll
  for (int i=0;i<3;i++){
    int c = threadIdx.x + i*256;
    float v = x[i]*inv*g[c] + b[c];
    g_h[(size_t)t*HH + c] = v;
    __nv_bfloat16 h,l; split_bf16_scalar(v, h, l);
    g_hhi[(size_t)t*HH + c] = h;
    g_hlo[(size_t)t*HH + c] = l;
  }
}

// ---------------- masked softmax (fp32 in -> bf16 hi/lo out, truncated) ------
__global__ void softmax_kernel()
{
  int z = blockIdx.y;
  int s = blockIdx.x;
  const size_t base = ((size_t)z*SS + s)*SS;
  const float* row = g_scores + base;
  const int L = (s < PLEN) ? PLEN : (s + 1);
  const int E = (s/128 + 1) * 128;
  float x[4];
  float mx = -3.4e38f;
  #pragma unroll
  for (int i=0;i<4;i++){
    int j = threadIdx.x + i*128;
    x[i] = (j < L) ? row[j] * 0.125f : -3.4e38f;
    mx = fmaxf(mx, x[i]);
  }
  mx = blockMax<4>(mx);
  float ls = 0.f;
  #pragma unroll
  for (int i=0;i<4;i++){
    int j = threadIdx.x + i*128;
    x[i] = (j < L) ? __expf(x[i] - mx) : 0.f;
    ls += x[i];
  }
  float sum = blockSum<4>(ls);
  float inv = 1.0f / sum;
  #pragma unroll
  for (int i=0;i<4;i++){
    int j = threadIdx.x + i*128;
    if (j < L){
      float v = x[i] * inv;
      __nv_bfloat16 h,l; split_bf16_scalar(v, h, l);
      g_schi[base + j] = h;
      g_sclo[base + j] = l;
    } else if (j < E){
      g_schi[base + j] = __float2bfloat16(0.f);
      g_sclo[base + j] = __float2bfloat16(0.f);
    }
  }
}

// ---------------- cross entropy (single pass, online logsumexp) --------------
__global__ void zero_loss_kernel(){ g_loss_sum = 0.f; }

__global__ void ce_kernel(const int* __restrict__ labels)
{
  int r = blockIdx.x;
  int bb = r / NVALID_PER_B;
  int s  = PLEN + (r - bb*NVALID_PER_B);
  const float* row = g_logits + (size_t)r*VV;
  int lab = labels[bb*SS + s];

  // per-thread online (max, sum) in one pass
  float mx = -3.4e38f;
  float sm = 0.f;
  for (int j = threadIdx.x; j < VV; j += 256){
    float v = row[j];
    if (v > mx){
      sm = sm * __expf(mx - v) + 1.0f;
      mx = v;
    } else {
      sm += __expf(v - mx);
    }
  }
  float bM = blockMax<8>(mx);
  float contrib = (sm > 0.f) ? sm * __expf(mx - bM) : 0.f;
  float total = blockSum<8>(contrib);
  if (threadIdx.x == 0){
    float nll = (logf(total) + bM) - row[lab];
    atomicAdd(&g_loss_sum, nll);
  }
}

__global__ void finalize_kernel(float* out){
  out[0] = g_loss_sum * (1.0f/(float)NVALID);
}

// ---------------- host orchestration -----------------------------------------
template<int BN, bool TRANSB, int ACT, int OUT, int MASK>
static void launch_mm(const __nv_bfloat16* Ah, const __nv_bfloat16* Al,
                      const __nv_bfloat16* Bh, const __nv_bfloat16* Bl,
                      const float* bias,
                      float* Cf, __nv_bfloat16* Ch, __nv_bfloat16* Cl,
                      int M, int N, int K, int lda, int ldb, int ldc,
                      int batchInner,
                      long long sA1, long long sA2, long long sB1, long long sB2,
                      long long sC1, long long sC2, int gz)
{
  constexpr int AP = 40;
  constexpr int BROWS = TRANSB ? BN : 32;
  constexpr int BP = TRANSB ? 40 : (BN + 8);
  constexpr int STAGE_EL = 2*128*AP + 2*BROWS*BP;
  int smemsz = 3 * STAGE_EL * (int)sizeof(__nv_bfloat16);
  cudaFuncSetAttribute(gemm_mma<BN,TRANSB,ACT,OUT,MASK>,
                       cudaFuncAttributeMaxDynamicSharedMemorySize, smemsz);
  dim3 grid((N + BN - 1)/BN, M/128, gz);
  gemm_mma<BN,TRANSB,ACT,OUT,MASK><<<grid, 256, smemsz>>>(
      Ah, Al, Bh, Bl, bias, Cf, Ch, Cl, M, N, K, lda, ldb, ldc,
      batchInner, sA1, sA2, sB1, sB2, sC1, sC2);
}

extern "C" void kernel_launch(void* const* d_in, const int* in_sizes, int n_in,
                              void* d_out, int out_size)
{
  const int*   input_ids = (const int*)  d_in[0];
  const int*   labels    = (const int*)  d_in[1];
  const float* word_emb  = (const float*)d_in[2];
  const float* pos_emb   = (const float*)d_in[3];
  const float* type_emb  = (const float*)d_in[4];
  const float* eg        = (const float*)d_in[5];
  const float* eb        = (const float*)d_in[6];
  const float* Wq = (const float*)d_in[7];  const float* bq = (const float*)d_in[8];
  const float* Wk = (const float*)d_in[9];  const float* bk = (const float*)d_in[10];
  const float* Wv = (const float*)d_in[11]; const float* bv = (const float*)d_in[12];
  const float* Wo = (const float*)d_in[13]; const float* bo = (const float*)d_in[14];
  const float* ln1g = (const float*)d_in[15]; const float* ln1b = (const float*)d_in[16];
  const float* W1 = (const float*)d_in[17]; const float* bf1 = (const float*)d_in[18];
  const float* W2 = (const float*)d_in[19]; const float* bf2 = (const float*)d_in[20];
  const float* ln2g = (const float*)d_in[21]; const float* ln2b = (const float*)d_in[22];
  const float* Wc = (const float*)d_in[23]; const float* bc = (const float*)d_in[24];
  float* out = (float*)d_out;

  float *p_tmp, *p_sc, *p_lg, *p_bqkv;
  __nv_bfloat16 *p_hhi, *p_hlo, *p_qkvh, *p_qkvl, *p_ctxh, *p_ctxl;
  __nv_bfloat16 *p_ffnh, *p_ffnl, *p_schi, *p_sclo;
  __nv_bfloat16 *p_wqkvh, *p_wqkvl, *p_woh, *p_wol, *p_w1h, *p_w1l, *p_w2h, *p_w2l, *p_wch, *p_wcl;
  cudaGetSymbolAddress((void**)&p_tmp,  g_tmp);
  cudaGetSymbolAddress((void**)&p_sc,   g_scores);
  cudaGetSymbolAddress((void**)&p_lg,   g_logits);
  cudaGetSymbolAddress((void**)&p_bqkv, g_bqkv);
  cudaGetSymbolAddress((void**)&p_hhi,  g_hhi);
  cudaGetSymbolAddress((void**)&p_hlo,  g_hlo);
  cudaGetSymbolAddress((void**)&p_qkvh, g_qkvh);
  cudaGetSymbolAddress((void**)&p_qkvl, g_qkvl);
  cudaGetSymbolAddress((void**)&p_ctxh, g_ctxh);
  cudaGetSymbolAddress((void**)&p_ctxl, g_ctxl);
  cudaGetSymbolAddress((void**)&p_ffnh, g_ffnh);
  cudaGetSymbolAddress((void**)&p_ffnl, g_ffnl);
  cudaGetSymbolAddress((void**)&p_schi, g_schi);
  cudaGetSymbolAddress((void**)&p_sclo, g_sclo);
  cudaGetSymbolAddress((void**)&p_wqkvh, g_wqkvh);
  cudaGetSymbolAddress((void**)&p_wqkvl, g_wqkvl);
  cudaGetSymbolAddress((void**)&p_woh, g_woh);
  cudaGetSymbolAddress((void**)&p_wol, g_wol);
  cudaGetSymbolAddress((void**)&p_w1h, g_w1h);
  cudaGetSymbolAddress((void**)&p_w1l, g_w1l);
  cudaGetSymbolAddress((void**)&p_w2h, g_w2h);
  cudaGetSymbolAddress((void**)&p_w2l, g_w2l);
  cudaGetSymbolAddress((void**)&p_wch, g_wch);
  cudaGetSymbolAddress((void**)&p_wcl, g_wcl);

  zero_loss_kernel<<<1,1>>>();
  pack_qkv_split_kernel<<<1024,256>>>(Wq, Wk, Wv, bq, bk, bv);
  split2_kernel<<<1024,256>>>(Wo, p_woh, p_wol, (size_t)LL*HH*HH/2);
  split2_kernel<<<1024,256>>>(W1, p_w1h, p_w1l, (size_t)LL*HH*FFF/2);
  split2_kernel<<<1024,256>>>(W2, p_w2h, p_w2l, (size_t)LL*FFF*HH/2);
  split2_kernel<<<1024,256>>>(Wc, p_wch, p_wcl, (size_t)HH*VV/2);
  embed_ln_kernel<<<NTOK,256>>>(input_ids, word_emb, pos_emb, type_emb, eg, eb);

  const long long headStride = (long long)SS*HH;
  const long long qkvBatch   = (long long)SS*QKVW;
  const long long scStrideH  = (long long)SS*SS;
  const long long scStrideB  = (long long)NHH*SS*SS;

  for (int l = 0; l < LL; l++) {
    // fused QKV projection: [4096,768] @ [768,2304] + b -> bf16 hi/lo
    launch_mm<64,false,0,1,0>(p_hhi, p_hlo,
                              p_wqkvh + (size_t)l*HH*QKVW, p_wqkvl + (size_t)l*HH*QKVW,
                              p_bqkv + (size_t)l*QKVW,
                              nullptr, p_qkvh, p_qkvl,
                              NTOK, QKVW, HH, HH, QKVW, QKVW,
                              1, 0,0, 0,0, 0,0, 1);

    // scores = q @ k^T (NT), dead tiles skipped -> fp32
    launch_mm<64,true,0,0,1>(p_qkvh, p_qkvl, p_qkvh + HH, p_qkvl + HH,
                             nullptr, p_sc, nullptr, nullptr,
                             SS, SS, DHH, QKVW, QKVW, SS,
                             NHH,
                             qkvBatch, (long long)DHH,
                             qkvBatch, (long long)DHH,
                             scStrideB, scStrideH, BB*NHH);

    softmax_kernel<<<dim3(SS, BB*NHH), 128>>>();

    // ctx = attn @ v (NN), K truncated -> bf16 hi/lo
    launch_mm<64,false,0,1,2>(p_schi, p_sclo, p_qkvh + 2*HH, p_qkvl + 2*HH,
                              nullptr, nullptr, p_ctxh, p_ctxl,
                              SS, DHH, SS, SS, QKVW, HH,
                              NHH,
                              scStrideB, scStrideH,
                              qkvBatch, (long long)DHH,
                              headStride, (long long)DHH, BB*NHH);

    // output proj -> fp32 g_tmp, then residual LN
    launch_mm<64,false,0,0,0>(p_ctxh, p_ctxl,
                              p_woh + (size_t)l*HH*HH, p_wol + (size_t)l*HH*HH,
                              bo + (size_t)l*HH,
                              p_tmp, nullptr, nullptr,
                              NTOK, HH, HH, HH, HH, HH,
                              1, 0,0, 0,0, 0,0, 1);
    resln_kernel<<<NTOK,256>>>(p_tmp, ln1g + (size_t)l*HH, ln1b + (size_t)l*HH);

    // FFN1 (+GELU) -> bf16 hi/lo
    launch_mm<64,false,1,1,0>(p_hhi, p_hlo,
                              p_w1h + (size_t)l*HH*FFF, p_w1l + (size_t)l*HH*FFF,
                              bf1 + (size_t)l*FFF,
                              nullptr, p_ffnh, p_ffnl,
                              NTOK, FFF, HH, HH, FFF, FFF,
                              1, 0,0, 0,0, 0,0, 1);
    // FFN2 -> fp32 g_tmp, then residual LN
    launch_mm<64,false,0,0,0>(p_ffnh, p_ffnl,
                              p_w2h + (size_t)l*FFF*HH, p_w2l + (size_t)l*FFF*HH,
                              bf2 + (size_t)l*HH,
                              p_tmp, nullptr, nullptr,
                              NTOK, HH, FFF, FFF, HH, HH,
                              1, 0,0, 0,0, 0,0, 1);
    resln_kernel<<<NTOK,256>>>(p_tmp, ln2g + (size_t)l*HH, ln2b + (size_t)l*HH);
  }

  // logits for valid tokens only (rows s in [128,512) per batch, contiguous)
  launch_mm<64,false,0,0,0>(p_hhi + (size_t)PLEN*HH, p_hlo + (size_t)PLEN*HH,
                            p_wch, p_wcl, bc,
                            p_lg, nullptr, nullptr,
                            NVALID_PER_B, VV, HH, HH, VV, VV,
                            1,
                            (long long)SS*HH, 0,
                            0, 0,
                            (long long)NVALID_PER_B*VV, 0, BB);

  ce_kernel<<<NVALID,256>>>(labels);
  finalize_kernel<<<1,1>>>(out);
}